// round 3
// baseline (speedup 1.0000x reference)
#include <cuda_runtime.h>
#include <cuda_bf16.h>

// Problem constants (from reference)
#define BATCHES 8
#define NP 4096
#define STRIDE 4
#define KNN 32
#define NS (NP / STRIDE)          // 1024 samples per batch
#define NSAMP (BATCHES * NS)      // 8192
#define NPTS (BATCHES * NP)       // 32768
#define DIN 64
#define H1DIM 128
#define H2DIM 256

// Output layout (float32 concat of the reference tuple)
#define XOUT_OFF   0
#define POS_OFF    (NSAMP * H2DIM)                 // 2097152
#define BATCH_OFF  (POS_OFF + NSAMP * 3)           // 2121728
#define IDX_OFF    (BATCH_OFF + NSAMP)             // 2129920
#define TOTAL_OUT  (IDX_OFF + NSAMP)               // 2138112

// Scratch (static __device__ arrays: no allocation)
__device__ float g_xw1[NPTS * H1DIM];   // 16 MB: x @ W1[:64]
__device__ int   g_nbr[NSAMP * KNN];    // 1 MB : local neighbor indices

__device__ __forceinline__ unsigned long long umin64(unsigned long long a,
                                                     unsigned long long b) {
    return b < a ? b : a;
}

// ---------------------------------------------------------------------------
// Kernel 1: xw1[n][j] = sum_f x[n][f] * W1[f][j]   (f < 64)
// ---------------------------------------------------------------------------
__global__ void __launch_bounds__(128) k_xw1(const float* __restrict__ x,
                                             const float* __restrict__ W1) {
    __shared__ float xs[8 * DIN];
    const int p0 = blockIdx.x * 8;
    const int tid = threadIdx.x;   // 128, tid == output channel j
    for (int i = tid; i < 8 * DIN; i += 128) xs[i] = x[p0 * DIN + i];
    __syncthreads();

    float acc[8];
#pragma unroll
    for (int p = 0; p < 8; ++p) acc[p] = 0.f;
#pragma unroll
    for (int f = 0; f < DIN; ++f) {
        float w = W1[f * H1DIM + tid];
#pragma unroll
        for (int p = 0; p < 8; ++p) acc[p] = fmaf(xs[p * DIN + f], w, acc[p]);
    }
#pragma unroll
    for (int p = 0; p < 8; ++p) g_xw1[(p0 + p) * H1DIM + tid] = acc[p];
}

// ---------------------------------------------------------------------------
// Kernel 2: KNN v2 (kept from round 2 — same neighbor sets, no barriers).
// One block (256 threads) = 16 samples of one batch.
// Phase 1: each WARP selects top-32 of its 512 points via 32 rounds of warp
//          argmin over u64 (flipped-d2 | idx) keys held in registers.
// Phase 2: one warp merges the 8 sorted 32-lists while the others proceed.
// d2 arithmetic bit-identical to round 1 (rel_err 7.374e-4, passing).
// ---------------------------------------------------------------------------
#define SPB2 16

__global__ void __launch_bounds__(256) k_knn(const float* __restrict__ pos) {
    extern __shared__ float sm[];
    float* px = sm;
    float* py = sm + NP;
    float* pz = sm + 2 * NP;
    unsigned long long* mbuf = (unsigned long long*)(sm + 3 * NP);  // [2][256]

    const int tid  = threadIdx.x;
    const int lane = tid & 31;
    const int wid  = tid >> 5;
    const int blk  = blockIdx.x;             // 512
    const int b    = blk / (NS / SPB2);
    const int grp  = blk % (NS / SPB2);

    for (int i = tid; i < NP; i += 256) {
        px[i] = pos[(b * NP + i) * 3 + 0];
        py[i] = pos[(b * NP + i) * 3 + 1];
        pz[i] = pos[(b * NP + i) * 3 + 2];
    }
    __syncthreads();

    for (int si = 0; si < SPB2; ++si) {
        const int s_local = grp * SPB2 + si;
        const int c_local = s_local * STRIDE;
        const float ax = px[c_local], ay = py[c_local], az = pz[c_local];
        const float as2 = __fadd_rn(__fadd_rn(__fmul_rn(ax, ax), __fmul_rn(ay, ay)),
                                    __fmul_rn(az, az));

        unsigned long long keys[16];
#pragma unroll
        for (int t = 0; t < 16; ++t) {
            const int i = tid + t * 256;
            const float bx = px[i], by = py[i], bz = pz[i];
            const float bn2 = __fadd_rn(__fadd_rn(__fmul_rn(bx, bx), __fmul_rn(by, by)),
                                        __fmul_rn(bz, bz));
            const float dot = __fadd_rn(__fadd_rn(__fmul_rn(ax, bx), __fmul_rn(ay, by)),
                                        __fmul_rn(az, bz));
            const float d2  = __fadd_rn(__fadd_rn(as2, bn2), -__fmul_rn(2.0f, dot));
            unsigned u = __float_as_uint(d2);
            unsigned kk = (u & 0x80000000u) ? ~u : (u | 0x80000000u);
            keys[t] = (((unsigned long long)kk) << 32) | (unsigned)i;
        }
        unsigned long long lmin = keys[0];
#pragma unroll
        for (int t = 1; t < 16; ++t) lmin = umin64(lmin, keys[t]);

        // Phase 1: warp-local top-32 (ascending), no barriers.
        unsigned long long mywin = 0;
        for (int r = 0; r < KNN; ++r) {
            unsigned long long w = lmin;
#pragma unroll
            for (int o = 16; o > 0; o >>= 1) {
                unsigned long long v = __shfl_xor_sync(0xffffffffu, w, o);
                w = umin64(w, v);
            }
            if (lane == r) mywin = w;
            if (lmin == w) {   // unique owner (idx embedded in key)
#pragma unroll
                for (int t = 0; t < 16; ++t)
                    if (keys[t] == w) keys[t] = 0xffffffffffffffffull;
                lmin = keys[0];
#pragma unroll
                for (int t = 1; t < 16; ++t) lmin = umin64(lmin, keys[t]);
            }
        }
        mbuf[(si & 1) * 256 + wid * 32 + lane] = mywin;
        __syncthreads();

        // Phase 2: warp (si & 7) merges; other warps proceed to next sample.
        if (wid == (si & 7)) {
            const int sidx = b * NS + s_local;
            unsigned long long mk[8];
#pragma unroll
            for (int t = 0; t < 8; ++t) mk[t] = mbuf[(si & 1) * 256 + lane + 32 * t];
            unsigned long long lm2 = mk[0];
#pragma unroll
            for (int t = 1; t < 8; ++t) lm2 = umin64(lm2, mk[t]);
            for (int r = 0; r < KNN; ++r) {
                unsigned long long w = lm2;
#pragma unroll
                for (int o = 16; o > 0; o >>= 1) {
                    unsigned long long v = __shfl_xor_sync(0xffffffffu, w, o);
                    w = umin64(w, v);
                }
                if (lane == r) g_nbr[sidx * KNN + r] = (int)(unsigned)(w & 0xffffffffull);
                if (lm2 == w) {
#pragma unroll
                    for (int t = 0; t < 8; ++t)
                        if (mk[t] == w) mk[t] = 0xffffffffffffffffull;
                    lm2 = mk[0];
#pragma unroll
                    for (int t = 1; t < 8; ++t) lm2 = umin64(lm2, mk[t]);
                }
            }
        }
    }
}

// ---------------------------------------------------------------------------
// Kernel 3: MLP + max-pool (round-1 proven version, plain FFMA).
// One block = 4 samples, 256 threads = 256 output channels. W2 column lives
// in 128 registers. Two neighbors per iteration (two independent FFMA
// chains), h1 double-buffered in smem.
// ---------------------------------------------------------------------------
#define SPB3 4

__global__ void __launch_bounds__(256, 1) k_mlp(const float* __restrict__ pos,
                                                const float* __restrict__ W1,
                                                const float* __restrict__ b1,
                                                const float* __restrict__ W2,
                                                const float* __restrict__ b2,
                                                float* __restrict__ out,
                                                int write_extras) {
    __shared__ float h1s[2][2][H1DIM];  // [parity][neighbor-half][j]
    __shared__ float w1r[3][H1DIM];
    __shared__ float b1s[H1DIM];

    const int tid = threadIdx.x;       // 256, tid == output channel c
    const int blk = blockIdx.x;        // NSAMP/SPB3 = 2048

    if (tid < H1DIM) {
        w1r[0][tid] = W1[64 * H1DIM + tid];
        w1r[1][tid] = W1[65 * H1DIM + tid];
        w1r[2][tid] = W1[66 * H1DIM + tid];
        b1s[tid]    = b1[tid];
    }
    float w2c[H1DIM];
#pragma unroll
    for (int j = 0; j < H1DIM; ++j) w2c[j] = W2[j * H2DIM + tid];
    const float b2c = b2[tid];
    __syncthreads();

    const int j    = tid & 127;
    const int half = tid >> 7;

    for (int si = 0; si < SPB3; ++si) {
        const int s       = blk * SPB3 + si;
        const int b       = s >> 10;            // / NS
        const int s_local = s & (NS - 1);
        const int p       = b * NP + s_local * STRIDE;
        const float psx = pos[3 * p], psy = pos[3 * p + 1], psz = pos[3 * p + 2];

        float acc_max = -3.402823466e38f;
        for (int kk = 0; kk < KNN; kk += 2) {
            const int parity = (kk >> 1) & 1;
            // produce h1 for two neighbors (128 threads each)
            const int nl = g_nbr[s * KNN + kk + half];
            const int g  = b * NP + nl;
            float rx = pos[3 * g]     - psx;
            float ry = pos[3 * g + 1] - psy;
            float rz = pos[3 * g + 2] - psz;
            float v = g_xw1[g * H1DIM + j];
            v = fmaf(rx, w1r[0][j], v);
            v = fmaf(ry, w1r[1][j], v);
            v = fmaf(rz, w1r[2][j], v);
            v += b1s[j];
            h1s[parity][half][j] = fmaxf(v, 0.f);
            __syncthreads();

            const float4* ha = (const float4*)h1s[parity][0];
            const float4* hb = (const float4*)h1s[parity][1];
            float acc_a = b2c, acc_b = b2c;
#pragma unroll
            for (int q = 0; q < 32; ++q) {
                const float4 a  = ha[q];
                const float4 bb = hb[q];
                acc_a = fmaf(a.x,  w2c[4 * q + 0], acc_a);
                acc_b = fmaf(bb.x, w2c[4 * q + 0], acc_b);
                acc_a = fmaf(a.y,  w2c[4 * q + 1], acc_a);
                acc_b = fmaf(bb.y, w2c[4 * q + 1], acc_b);
                acc_a = fmaf(a.z,  w2c[4 * q + 2], acc_a);
                acc_b = fmaf(bb.z, w2c[4 * q + 2], acc_b);
                acc_a = fmaf(a.w,  w2c[4 * q + 3], acc_a);
                acc_b = fmaf(bb.w, w2c[4 * q + 3], acc_b);
            }
            acc_max = fmaxf(acc_max, fmaxf(acc_a, 0.f));
            acc_max = fmaxf(acc_max, fmaxf(acc_b, 0.f));
            // no trailing sync needed: next iteration writes the other buffer
        }
        out[XOUT_OFF + s * H2DIM + tid] = acc_max;
        if (write_extras) {
            if (tid < 3)  out[POS_OFF + s * 3 + tid] = pos[3 * p + tid];
            if (tid == 3) out[BATCH_OFF + s] = (float)b;
            if (tid == 4) out[IDX_OFF + s]   = (float)p;
        }
    }
}

// ---------------------------------------------------------------------------
extern "C" void kernel_launch(void* const* d_in, const int* in_sizes, int n_in,
                              void* d_out, int out_size) {
    const float* x   = (const float*)d_in[0];
    const float* pos = (const float*)d_in[1];
    // d_in[2] = batch (int64), derivable -> unused
    const float* W1  = (const float*)d_in[3];
    const float* b1  = (const float*)d_in[4];
    const float* W2  = (const float*)d_in[5];
    const float* b2  = (const float*)d_in[6];
    float* out = (float*)d_out;

    const int write_extras = (out_size >= TOTAL_OUT) ? 1 : 0;

    k_xw1<<<NPTS / 8, 128>>>(x, W1);

    const int smem2 = (3 * NP) * (int)sizeof(float) + 2 * 256 * (int)sizeof(unsigned long long);
    cudaFuncSetAttribute(k_knn, cudaFuncAttributeMaxDynamicSharedMemorySize, smem2);
    k_knn<<<BATCHES * (NS / SPB2), 256, smem2>>>(pos);

    k_mlp<<<NSAMP / SPB3, 256>>>(pos, W1, b1, W2, b2, out, write_extras);
}

// round 4
// speedup vs baseline: 1.4750x; 1.4750x over previous
#include <cuda_runtime.h>
#include <cuda_bf16.h>

// Problem constants (from reference)
#define BATCHES 8
#define NP 4096
#define STRIDE 4
#define KNN 32
#define NS (NP / STRIDE)          // 1024 samples per batch
#define NSAMP (BATCHES * NS)      // 8192
#define NPTS (BATCHES * NP)       // 32768
#define DIN 64
#define H1DIM 128
#define H2DIM 256

// Output layout (float32 concat of the reference tuple)
#define XOUT_OFF   0
#define POS_OFF    (NSAMP * H2DIM)                 // 2097152
#define BATCH_OFF  (POS_OFF + NSAMP * 3)           // 2121728
#define IDX_OFF    (BATCH_OFF + NSAMP)             // 2129920
#define TOTAL_OUT  (IDX_OFF + NSAMP)               // 2138112

// Scratch (static __device__ arrays: no allocation)
__device__ float g_xw1[NPTS * H1DIM];   // 16 MB: x @ W1[:64]
__device__ int   g_nbr[NSAMP * KNN];    // 1 MB : local neighbor indices

__device__ __forceinline__ unsigned long long umin64(unsigned long long a,
                                                     unsigned long long b) {
    return b < a ? b : a;
}

// packed fp32x2 FMA (sm_100+): two independent exact fp32 FMAs per instruction
__device__ __forceinline__ void fma2(unsigned long long& a, unsigned long long x,
                                     unsigned long long w) {
    asm("fma.rn.f32x2 %0, %1, %2, %0;" : "+l"(a) : "l"(x), "l"(w));
}
__device__ __forceinline__ float red2(unsigned long long a, float bias) {
    float lo, hi;
    asm("mov.b64 {%0, %1}, %2;" : "=f"(lo), "=f"(hi) : "l"(a));
    return lo + hi + bias;
}

// ---------------------------------------------------------------------------
// Kernel 1: xw1[n][j] = sum_f x[n][f] * W1[f][j]   (f < 64)   [R1, unchanged]
// ---------------------------------------------------------------------------
__global__ void __launch_bounds__(128) k_xw1(const float* __restrict__ x,
                                             const float* __restrict__ W1) {
    __shared__ float xs[8 * DIN];
    const int p0 = blockIdx.x * 8;
    const int tid = threadIdx.x;   // 128, tid == output channel j
    for (int i = tid; i < 8 * DIN; i += 128) xs[i] = x[p0 * DIN + i];
    __syncthreads();

    float acc[8];
#pragma unroll
    for (int p = 0; p < 8; ++p) acc[p] = 0.f;
#pragma unroll
    for (int f = 0; f < DIN; ++f) {
        float w = W1[f * H1DIM + tid];
#pragma unroll
        for (int p = 0; p < 8; ++p) acc[p] = fmaf(xs[p * DIN + f], w, acc[p]);
    }
#pragma unroll
    for (int p = 0; p < 8; ++p) g_xw1[(p0 + p) * H1DIM + tid] = acc[p];
}

// ---------------------------------------------------------------------------
// Kernel 2: KNN v1 (round-1 proven version). One block = 16 samples of one
// batch; 32 rounds of block-wide argmin over (d2, idx) packed u64 keys.
// d2 computed with the reference's exact rounding (no FMA contraction).
// ---------------------------------------------------------------------------
#define SPB2 16

__global__ void __launch_bounds__(256) k_knn(const float* __restrict__ pos) {
    extern __shared__ float sm[];
    float* px = sm;
    float* py = sm + NP;
    float* pz = sm + 2 * NP;
    __shared__ unsigned long long warpmin[8];
    __shared__ unsigned long long winner;

    const int tid = threadIdx.x;            // 256
    const int blk = blockIdx.x;             // 8 * 64 = 512
    const int b   = blk / (NS / SPB2);
    const int grp = blk % (NS / SPB2);

    for (int i = tid; i < NP; i += 256) {
        px[i] = pos[(b * NP + i) * 3 + 0];
        py[i] = pos[(b * NP + i) * 3 + 1];
        pz[i] = pos[(b * NP + i) * 3 + 2];
    }
    __syncthreads();

    for (int si = 0; si < SPB2; ++si) {
        const int s_local = grp * SPB2 + si;
        const int c_local = s_local * STRIDE;
        const float ax = px[c_local], ay = py[c_local], az = pz[c_local];
        const float as2 = __fadd_rn(__fadd_rn(__fmul_rn(ax, ax), __fmul_rn(ay, ay)),
                                    __fmul_rn(az, az));

        unsigned long long keys[16];
#pragma unroll
        for (int t = 0; t < 16; ++t) {
            const int i = tid + t * 256;
            const float bx = px[i], by = py[i], bz = pz[i];
            const float bn2 = __fadd_rn(__fadd_rn(__fmul_rn(bx, bx), __fmul_rn(by, by)),
                                        __fmul_rn(bz, bz));
            const float dot = __fadd_rn(__fadd_rn(__fmul_rn(ax, bx), __fmul_rn(ay, by)),
                                        __fmul_rn(az, bz));
            const float d2  = __fadd_rn(__fadd_rn(as2, bn2), -__fmul_rn(2.0f, dot));
            unsigned u = __float_as_uint(d2);
            unsigned kk = (u & 0x80000000u) ? ~u : (u | 0x80000000u);
            keys[t] = (((unsigned long long)kk) << 32) | (unsigned)i;
        }
        unsigned long long lmin = keys[0];
#pragma unroll
        for (int t = 1; t < 16; ++t) lmin = umin64(lmin, keys[t]);

        const int sidx = b * NS + s_local;
        for (int r = 0; r < KNN; ++r) {
            unsigned long long v = lmin;
#pragma unroll
            for (int o = 16; o > 0; o >>= 1)
                v = umin64(v, __shfl_down_sync(0xffffffffu, v, o));
            if ((tid & 31) == 0) warpmin[tid >> 5] = v;
            __syncthreads();
            if (tid == 0) {
                unsigned long long w = warpmin[0];
#pragma unroll
                for (int q = 1; q < 8; ++q) w = umin64(w, warpmin[q]);
                winner = w;
                g_nbr[sidx * KNN + r] = (int)(unsigned)(w & 0xffffffffull);
            }
            __syncthreads();
            const unsigned long long w = winner;
            if (lmin == w) {   // unique owner (idx embedded in key)
#pragma unroll
                for (int t = 0; t < 16; ++t)
                    if (keys[t] == w) keys[t] = 0xffffffffffffffffull;
                lmin = keys[0];
#pragma unroll
                for (int t = 1; t < 16; ++t) lmin = umin64(lmin, keys[t]);
            }
        }
        __syncthreads();
    }
}

// ---------------------------------------------------------------------------
// Kernel 3: MLP + max-pool with packed f32x2 FMAs (round-2 proven version).
// One block = 4 samples, 256 threads = 256 output channels. W2 column lives
// in 64 packed u64 registers. All 32 h1 vectors of a sample are produced in
// smem up front (1 sync), then consumed 4 neighbors at a time with 4
// independent f32x2 accumulator chains.
// ---------------------------------------------------------------------------
#define SPB3 4

__global__ void __launch_bounds__(256, 1) k_mlp(const float* __restrict__ pos,
                                                const float* __restrict__ W1,
                                                const float* __restrict__ b1,
                                                const float* __restrict__ W2,
                                                const float* __restrict__ b2,
                                                float* __restrict__ out,
                                                int write_extras) {
    __shared__ __align__(16) float h1s[KNN][H1DIM];   // 16 KB
    __shared__ float w1r[3][H1DIM];
    __shared__ float b1s[H1DIM];
    __shared__ float npx[KNN], npy[KNN], npz[KNN];
    __shared__ int   gix[KNN];

    const int tid = threadIdx.x;       // 256, tid == output channel c
    const int blk = blockIdx.x;        // NSAMP/SPB3 = 2048

    if (tid < H1DIM) {
        w1r[0][tid] = W1[64 * H1DIM + tid];
        w1r[1][tid] = W1[65 * H1DIM + tid];
        w1r[2][tid] = W1[66 * H1DIM + tid];
        b1s[tid]    = b1[tid];
    }
    // Pack this thread's W2 column as 64 f32x2 pairs (adjacent j).
    unsigned long long w2p[64];
#pragma unroll
    for (int q = 0; q < 64; ++q) {
        float w0 = W2[(2 * q) * H2DIM + tid];
        float w1v = W2[(2 * q + 1) * H2DIM + tid];
        asm("mov.b64 %0, {%1, %2};" : "=l"(w2p[q]) : "f"(w0), "f"(w1v));
    }
    const float b2c = b2[tid];
    const int j    = tid & 127;
    const int half = tid >> 7;
    __syncthreads();

    for (int si = 0; si < SPB3; ++si) {
        const int s       = blk * SPB3 + si;
        const int b       = s >> 10;            // / NS
        const int s_local = s & (NS - 1);
        const int p       = b * NP + s_local * STRIDE;
        const float psx = pos[3 * p], psy = pos[3 * p + 1], psz = pos[3 * p + 2];

        if (tid < KNN) {
            int nl = g_nbr[s * KNN + tid];
            int g  = b * NP + nl;
            gix[tid] = g;
            npx[tid] = pos[3 * g];
            npy[tid] = pos[3 * g + 1];
            npz[tid] = pos[3 * g + 2];
        }
        __syncthreads();

        // Produce all 32 h1 vectors (each thread makes 16 values).
#pragma unroll
        for (int kk = 0; kk < 16; ++kk) {
            const int k = kk * 2 + half;
            const int g = gix[k];
            float rx = npx[k] - psx;
            float ry = npy[k] - psy;
            float rz = npz[k] - psz;
            float v = g_xw1[g * H1DIM + j];
            v = fmaf(rx, w1r[0][j], v);
            v = fmaf(ry, w1r[1][j], v);
            v = fmaf(rz, w1r[2][j], v);
            v += b1s[j];
            h1s[k][j] = fmaxf(v, 0.f);
        }
        __syncthreads();

        // Consume: 4 neighbors per iteration, 4 independent f32x2 chains.
        float amax = -3.402823466e38f;
#pragma unroll
        for (int kq = 0; kq < 8; ++kq) {
            const ulonglong2* h0 = (const ulonglong2*)h1s[4 * kq + 0];
            const ulonglong2* h1 = (const ulonglong2*)h1s[4 * kq + 1];
            const ulonglong2* h2 = (const ulonglong2*)h1s[4 * kq + 2];
            const ulonglong2* h3 = (const ulonglong2*)h1s[4 * kq + 3];
            unsigned long long a0 = 0, a1 = 0, a2 = 0, a3 = 0;
#pragma unroll
            for (int q = 0; q < 32; ++q) {
                const ulonglong2 v0 = h0[q];
                const ulonglong2 v1 = h1[q];
                const ulonglong2 v2 = h2[q];
                const ulonglong2 v3 = h3[q];
                fma2(a0, v0.x, w2p[2 * q]); fma2(a0, v0.y, w2p[2 * q + 1]);
                fma2(a1, v1.x, w2p[2 * q]); fma2(a1, v1.y, w2p[2 * q + 1]);
                fma2(a2, v2.x, w2p[2 * q]); fma2(a2, v2.y, w2p[2 * q + 1]);
                fma2(a3, v3.x, w2p[2 * q]); fma2(a3, v3.y, w2p[2 * q + 1]);
            }
            amax = fmaxf(amax, fmaxf(red2(a0, b2c), 0.f));
            amax = fmaxf(amax, fmaxf(red2(a1, b2c), 0.f));
            amax = fmaxf(amax, fmaxf(red2(a2, b2c), 0.f));
            amax = fmaxf(amax, fmaxf(red2(a3, b2c), 0.f));
        }
        out[XOUT_OFF + s * H2DIM + tid] = amax;
        if (write_extras) {
            if (tid < 3)  out[POS_OFF + s * 3 + tid] = pos[3 * p + tid];
            if (tid == 3) out[BATCH_OFF + s] = (float)b;
            if (tid == 4) out[IDX_OFF + s]   = (float)p;
        }
        __syncthreads();   // h1s/npx reused next sample
    }
}

// ---------------------------------------------------------------------------
extern "C" void kernel_launch(void* const* d_in, const int* in_sizes, int n_in,
                              void* d_out, int out_size) {
    const float* x   = (const float*)d_in[0];
    const float* pos = (const float*)d_in[1];
    // d_in[2] = batch (int64), derivable -> unused
    const float* W1  = (const float*)d_in[3];
    const float* b1  = (const float*)d_in[4];
    const float* W2  = (const float*)d_in[5];
    const float* b2  = (const float*)d_in[6];
    float* out = (float*)d_out;

    const int write_extras = (out_size >= TOTAL_OUT) ? 1 : 0;

    k_xw1<<<NPTS / 8, 128>>>(x, W1);

    const int smem2 = 3 * NP * (int)sizeof(float);   // 48 KB
    cudaFuncSetAttribute(k_knn, cudaFuncAttributeMaxDynamicSharedMemorySize, smem2);
    k_knn<<<BATCHES * (NS / SPB2), 256, smem2>>>(pos);

    k_mlp<<<NSAMP / SPB3, 256>>>(pos, W1, b1, W2, b2, out, write_extras);
}

// round 5
// speedup vs baseline: 1.9643x; 1.3317x over previous
#include <cuda_runtime.h>
#include <cuda_bf16.h>

// Problem constants (from reference)
#define BATCHES 8
#define NP 4096
#define STRIDE 4
#define KNN 32
#define NS (NP / STRIDE)          // 1024 samples per batch
#define NSAMP (BATCHES * NS)      // 8192
#define NPTS (BATCHES * NP)       // 32768
#define DIN 64
#define H1DIM 128
#define H2DIM 256

// Output layout (float32 concat of the reference tuple)
#define XOUT_OFF   0
#define POS_OFF    (NSAMP * H2DIM)                 // 2097152
#define BATCH_OFF  (POS_OFF + NSAMP * 3)           // 2121728
#define IDX_OFF    (BATCH_OFF + NSAMP)             // 2129920
#define TOTAL_OUT  (IDX_OFF + NSAMP)               // 2138112

// Scratch (static __device__ arrays: no allocation)
__device__ float g_xw1[NPTS * H1DIM];   // 16 MB: x @ W1[:64]
__device__ int   g_nbr[NSAMP * KNN];    // 1 MB : local neighbor indices

__device__ __forceinline__ unsigned long long umin64(unsigned long long a,
                                                     unsigned long long b) {
    return b < a ? b : a;
}
__device__ __forceinline__ unsigned long long umax64(unsigned long long a,
                                                     unsigned long long b) {
    return a < b ? b : a;
}

// packed fp32x2 FMA (sm_100+): two independent exact fp32 FMAs per instruction
__device__ __forceinline__ void fma2(unsigned long long& a, unsigned long long x,
                                     unsigned long long w) {
    asm("fma.rn.f32x2 %0, %1, %2, %0;" : "+l"(a) : "l"(x), "l"(w));
}
__device__ __forceinline__ float red2(unsigned long long a, float bias) {
    float lo, hi;
    asm("mov.b64 {%0, %1}, %2;" : "=f"(lo), "=f"(hi) : "l"(a));
    return lo + hi + bias;
}

// ---------------------------------------------------------------------------
// Warp-cooperative bitonic sort of N = R*32 u64 keys (R regs/lane).
// Virtual index v = r*32 + lane; result ascending in v.
// ---------------------------------------------------------------------------
template <int R>
__device__ __forceinline__ void bitonic_sort(unsigned long long k[R], int lane) {
    const int N = R * 32;
#pragma unroll
    for (int kk = 2; kk <= N; kk <<= 1) {
#pragma unroll
        for (int j = kk >> 1; j > 0; j >>= 1) {
            if (j >= 32) {
                const int rj = j >> 5;
#pragma unroll
                for (int r = 0; r < R; ++r) {
                    if ((r & rj) == 0) {
                        const int r2 = r | rj;
                        const bool asc = (((r * 32) & kk) == 0);
                        const unsigned long long lo = umin64(k[r], k[r2]);
                        const unsigned long long hi = umax64(k[r], k[r2]);
                        k[r]  = asc ? lo : hi;
                        k[r2] = asc ? hi : lo;
                    }
                }
            } else {
#pragma unroll
                for (int r = 0; r < R; ++r) {
                    const unsigned long long other =
                        __shfl_xor_sync(0xffffffffu, k[r], j);
                    const int v = r * 32 + lane;
                    const bool asc     = ((v & kk) == 0);
                    const bool upper   = ((lane & j) != 0);
                    const bool keepMin = (asc != upper);
                    const unsigned long long mn = umin64(k[r], other);
                    const unsigned long long mx = umax64(k[r], other);
                    k[r] = keepMin ? mn : mx;
                }
            }
        }
    }
}

// ---------------------------------------------------------------------------
// Kernel 1: xw1[n][j] = sum_f x[n][f] * W1[f][j]   (f < 64)   [unchanged]
// ---------------------------------------------------------------------------
__global__ void __launch_bounds__(128) k_xw1(const float* __restrict__ x,
                                             const float* __restrict__ W1) {
    __shared__ float xs[8 * DIN];
    const int p0 = blockIdx.x * 8;
    const int tid = threadIdx.x;   // 128, tid == output channel j
    for (int i = tid; i < 8 * DIN; i += 128) xs[i] = x[p0 * DIN + i];
    __syncthreads();

    float acc[8];
#pragma unroll
    for (int p = 0; p < 8; ++p) acc[p] = 0.f;
#pragma unroll
    for (int f = 0; f < DIN; ++f) {
        float w = W1[f * H1DIM + tid];
#pragma unroll
        for (int p = 0; p < 8; ++p) acc[p] = fmaf(xs[p * DIN + f], w, acc[p]);
    }
#pragma unroll
    for (int p = 0; p < 8; ++p) g_xw1[(p0 + p) * H1DIM + tid] = acc[p];
}

// ---------------------------------------------------------------------------
// Kernel 2: KNN v3 — threshold-prune + warp-bitonic final selection.
// One block (256 threads) = 16 samples of one batch.
// Phase A (per sample, block-wide, 1 barrier):
//   - 16 keys/thread (d2 arithmetic bit-identical to proven v1)
//   - warp sorts its 32 thread-minima, takes 4th smallest -> T_w
//   - T = max_w T_w ; every key <= T compacted to a per-sample smem list.
//     Guarantee: >= 32 keys <= T, so the true top-32 are all in the list.
// Phase B (per warp, no barriers): bitonic sort the candidate list
//   (64/128/256 wide by count), write first 32 keys' indices in rank order.
// ---------------------------------------------------------------------------
#define SPB2 16
#define CAP  256

__global__ void __launch_bounds__(256) k_knn(const float* __restrict__ pos) {
    extern __shared__ float sm[];
    float* px = sm;
    float* py = sm + NP;
    float* pz = sm + 2 * NP;
    unsigned long long* lists = (unsigned long long*)(sm + 3 * NP); // [16][CAP]
    unsigned long long* warpT = lists + SPB2 * CAP;                 // [16][8]
    int* s_cnt = (int*)(warpT + SPB2 * 8);                          // [16]

    const int tid  = threadIdx.x;            // 256
    const int lane = tid & 31;
    const int wid  = tid >> 5;
    const int blk  = blockIdx.x;             // 512
    const int b    = blk / (NS / SPB2);
    const int grp  = blk % (NS / SPB2);

    for (int i = tid; i < NP; i += 256) {
        px[i] = pos[(b * NP + i) * 3 + 0];
        py[i] = pos[(b * NP + i) * 3 + 1];
        pz[i] = pos[(b * NP + i) * 3 + 2];
    }
    if (tid < SPB2) s_cnt[tid] = 0;
    __syncthreads();

    // ---- Phase A ----
    for (int si = 0; si < SPB2; ++si) {
        const int s_local = grp * SPB2 + si;
        const int c_local = s_local * STRIDE;
        const float ax = px[c_local], ay = py[c_local], az = pz[c_local];
        const float as2 = __fadd_rn(__fadd_rn(__fmul_rn(ax, ax), __fmul_rn(ay, ay)),
                                    __fmul_rn(az, az));

        unsigned long long keys[16];
#pragma unroll
        for (int t = 0; t < 16; ++t) {
            const int i = tid + t * 256;
            const float bx = px[i], by = py[i], bz = pz[i];
            const float bn2 = __fadd_rn(__fadd_rn(__fmul_rn(bx, bx), __fmul_rn(by, by)),
                                        __fmul_rn(bz, bz));
            const float dot = __fadd_rn(__fadd_rn(__fmul_rn(ax, bx), __fmul_rn(ay, by)),
                                        __fmul_rn(az, bz));
            const float d2  = __fadd_rn(__fadd_rn(as2, bn2), -__fmul_rn(2.0f, dot));
            unsigned u = __float_as_uint(d2);
            unsigned kk = (u & 0x80000000u) ? ~u : (u | 0x80000000u);
            keys[t] = (((unsigned long long)kk) << 32) | (unsigned)i;
        }
        unsigned long long lmin = keys[0];
#pragma unroll
        for (int t = 1; t < 16; ++t) lmin = umin64(lmin, keys[t]);

        // Warp threshold: 4th smallest of the warp's 32 thread-minima.
        unsigned long long tm[1] = { lmin };
        bitonic_sort<1>(tm, lane);
        const unsigned long long Tw = __shfl_sync(0xffffffffu, tm[0], 3);
        if (lane == 0) warpT[si * 8 + wid] = Tw;
        __syncthreads();

        unsigned long long T = warpT[si * 8 + 0];
#pragma unroll
        for (int q = 1; q < 8; ++q) T = umax64(T, warpT[si * 8 + q]);

        int cnt = 0;
#pragma unroll
        for (int t = 0; t < 16; ++t) cnt += (keys[t] <= T) ? 1 : 0;
        int base = atomicAdd(&s_cnt[si], cnt);
        unsigned long long* lst = lists + si * CAP;
#pragma unroll
        for (int t = 0; t < 16; ++t) {
            if (keys[t] <= T) {
                if (base < CAP) lst[base] = keys[t];
                ++base;
            }
        }
        // list writes consumed only after the phase-B barrier below
    }
    __syncthreads();

    // ---- Phase B: warp w finalizes samples w and w+8, no barriers ----
    for (int q = 0; q < 2; ++q) {
        const int si = wid + q * 8;
        int C = s_cnt[si];
        if (C > CAP) C = CAP;   // astronomically unlikely; clamp defensively
        const int s_local = grp * SPB2 + si;
        const int sidx = b * NS + s_local;
        const unsigned long long* lst = lists + si * CAP;

        if (C <= 64) {
            unsigned long long k2[2];
#pragma unroll
            for (int r = 0; r < 2; ++r) {
                const int v = r * 32 + lane;
                k2[r] = (v < C) ? lst[v] : 0xffffffffffffffffull;
            }
            bitonic_sort<2>(k2, lane);
            g_nbr[sidx * KNN + lane] = (int)(unsigned)(k2[0] & 0xffffffffull);
        } else if (C <= 128) {
            unsigned long long k4[4];
#pragma unroll
            for (int r = 0; r < 4; ++r) {
                const int v = r * 32 + lane;
                k4[r] = (v < C) ? lst[v] : 0xffffffffffffffffull;
            }
            bitonic_sort<4>(k4, lane);
            g_nbr[sidx * KNN + lane] = (int)(unsigned)(k4[0] & 0xffffffffull);
        } else {
            unsigned long long k8[8];
#pragma unroll
            for (int r = 0; r < 8; ++r) {
                const int v = r * 32 + lane;
                k8[r] = (v < C) ? lst[v] : 0xffffffffffffffffull;
            }
            bitonic_sort<8>(k8, lane);
            g_nbr[sidx * KNN + lane] = (int)(unsigned)(k8[0] & 0xffffffffull);
        }
    }
}

// ---------------------------------------------------------------------------
// Kernel 3: MLP + max-pool with packed f32x2 FMAs (proven R2/R4 version).
// ---------------------------------------------------------------------------
#define SPB3 4

__global__ void __launch_bounds__(256, 1) k_mlp(const float* __restrict__ pos,
                                                const float* __restrict__ W1,
                                                const float* __restrict__ b1,
                                                const float* __restrict__ W2,
                                                const float* __restrict__ b2,
                                                float* __restrict__ out,
                                                int write_extras) {
    __shared__ __align__(16) float h1s[KNN][H1DIM];   // 16 KB
    __shared__ float w1r[3][H1DIM];
    __shared__ float b1s[H1DIM];
    __shared__ float npx[KNN], npy[KNN], npz[KNN];
    __shared__ int   gix[KNN];

    const int tid = threadIdx.x;       // 256, tid == output channel c
    const int blk = blockIdx.x;        // NSAMP/SPB3 = 2048

    if (tid < H1DIM) {
        w1r[0][tid] = W1[64 * H1DIM + tid];
        w1r[1][tid] = W1[65 * H1DIM + tid];
        w1r[2][tid] = W1[66 * H1DIM + tid];
        b1s[tid]    = b1[tid];
    }
    // Pack this thread's W2 column as 64 f32x2 pairs (adjacent j).
    unsigned long long w2p[64];
#pragma unroll
    for (int q = 0; q < 64; ++q) {
        float w0 = W2[(2 * q) * H2DIM + tid];
        float w1v = W2[(2 * q + 1) * H2DIM + tid];
        asm("mov.b64 %0, {%1, %2};" : "=l"(w2p[q]) : "f"(w0), "f"(w1v));
    }
    const float b2c = b2[tid];
    const int j    = tid & 127;
    const int half = tid >> 7;
    __syncthreads();

    for (int si = 0; si < SPB3; ++si) {
        const int s       = blk * SPB3 + si;
        const int b       = s >> 10;            // / NS
        const int s_local = s & (NS - 1);
        const int p       = b * NP + s_local * STRIDE;
        const float psx = pos[3 * p], psy = pos[3 * p + 1], psz = pos[3 * p + 2];

        if (tid < KNN) {
            int nl = g_nbr[s * KNN + tid];
            int g  = b * NP + nl;
            gix[tid] = g;
            npx[tid] = pos[3 * g];
            npy[tid] = pos[3 * g + 1];
            npz[tid] = pos[3 * g + 2];
        }
        __syncthreads();

        // Produce all 32 h1 vectors (each thread makes 16 values).
#pragma unroll
        for (int kk = 0; kk < 16; ++kk) {
            const int k = kk * 2 + half;
            const int g = gix[k];
            float rx = npx[k] - psx;
            float ry = npy[k] - psy;
            float rz = npz[k] - psz;
            float v = g_xw1[g * H1DIM + j];
            v = fmaf(rx, w1r[0][j], v);
            v = fmaf(ry, w1r[1][j], v);
            v = fmaf(rz, w1r[2][j], v);
            v += b1s[j];
            h1s[k][j] = fmaxf(v, 0.f);
        }
        __syncthreads();

        // Consume: 4 neighbors per iteration, 4 independent f32x2 chains.
        float amax = -3.402823466e38f;
#pragma unroll
        for (int kq = 0; kq < 8; ++kq) {
            const ulonglong2* h0 = (const ulonglong2*)h1s[4 * kq + 0];
            const ulonglong2* h1 = (const ulonglong2*)h1s[4 * kq + 1];
            const ulonglong2* h2 = (const ulonglong2*)h1s[4 * kq + 2];
            const ulonglong2* h3 = (const ulonglong2*)h1s[4 * kq + 3];
            unsigned long long a0 = 0, a1 = 0, a2 = 0, a3 = 0;
#pragma unroll
            for (int q = 0; q < 32; ++q) {
                const ulonglong2 v0 = h0[q];
                const ulonglong2 v1 = h1[q];
                const ulonglong2 v2 = h2[q];
                const ulonglong2 v3 = h3[q];
                fma2(a0, v0.x, w2p[2 * q]); fma2(a0, v0.y, w2p[2 * q + 1]);
                fma2(a1, v1.x, w2p[2 * q]); fma2(a1, v1.y, w2p[2 * q + 1]);
                fma2(a2, v2.x, w2p[2 * q]); fma2(a2, v2.y, w2p[2 * q + 1]);
                fma2(a3, v3.x, w2p[2 * q]); fma2(a3, v3.y, w2p[2 * q + 1]);
            }
            amax = fmaxf(amax, fmaxf(red2(a0, b2c), 0.f));
            amax = fmaxf(amax, fmaxf(red2(a1, b2c), 0.f));
            amax = fmaxf(amax, fmaxf(red2(a2, b2c), 0.f));
            amax = fmaxf(amax, fmaxf(red2(a3, b2c), 0.f));
        }
        out[XOUT_OFF + s * H2DIM + tid] = amax;
        if (write_extras) {
            if (tid < 3)  out[POS_OFF + s * 3 + tid] = pos[3 * p + tid];
            if (tid == 3) out[BATCH_OFF + s] = (float)b;
            if (tid == 4) out[IDX_OFF + s]   = (float)p;
        }
        __syncthreads();   // h1s/npx reused next sample
    }
}

// ---------------------------------------------------------------------------
extern "C" void kernel_launch(void* const* d_in, const int* in_sizes, int n_in,
                              void* d_out, int out_size) {
    const float* x   = (const float*)d_in[0];
    const float* pos = (const float*)d_in[1];
    // d_in[2] = batch (int64), derivable -> unused
    const float* W1  = (const float*)d_in[3];
    const float* b1  = (const float*)d_in[4];
    const float* W2  = (const float*)d_in[5];
    const float* b2  = (const float*)d_in[6];
    float* out = (float*)d_out;

    const int write_extras = (out_size >= TOTAL_OUT) ? 1 : 0;

    k_xw1<<<NPTS / 8, 128>>>(x, W1);

    // pos tiles + candidate lists + warp thresholds + counters
    const int smem2 = 3 * NP * (int)sizeof(float)
                    + SPB2 * CAP * (int)sizeof(unsigned long long)
                    + SPB2 * 8 * (int)sizeof(unsigned long long)
                    + SPB2 * (int)sizeof(int);
    cudaFuncSetAttribute(k_knn, cudaFuncAttributeMaxDynamicSharedMemorySize, smem2);
    k_knn<<<BATCHES * (NS / SPB2), 256, smem2>>>(pos);

    k_mlp<<<NSAMP / SPB3, 256>>>(pos, W1, b1, W2, b2, out, write_extras);
}

// round 10
// speedup vs baseline: 3.5323x; 1.7982x over previous
#include <cuda_runtime.h>
#include <cuda_bf16.h>
#include <cstdint>

// Problem constants (from reference)
#define BATCHES 8
#define NP 4096
#define STRIDE 4
#define KNN 32
#define NS (NP / STRIDE)          // 1024 samples per batch
#define NSAMP (BATCHES * NS)      // 8192
#define NPTS (BATCHES * NP)       // 32768
#define DIN 64
#define H1DIM 128
#define H2DIM 256

// Output layout (float32 concat of the reference tuple)
#define XOUT_OFF   0
#define POS_OFF    (NSAMP * H2DIM)                 // 2097152
#define BATCH_OFF  (POS_OFF + NSAMP * 3)           // 2121728
#define IDX_OFF    (BATCH_OFF + NSAMP)             // 2129920
#define TOTAL_OUT  (IDX_OFF + NSAMP)               // 2138112

// Scratch (static __device__ arrays: no allocation)
__device__ float g_xw1[NPTS * H1DIM];     // 16 MB: x @ W1[:64]
__device__ int   g_nbr[NSAMP * KNN];      // 1 MB : local neighbor indices
// W2 packed as per-lane mma.sync B-fragments, bf16 hi/lo:
// flat index = hl*16384 + wid*2048 + kt*256 + t*64 + h*32 + lane
__device__ uint32_t g_w2frag[32768];      // 128 KB

__device__ __forceinline__ unsigned long long umin64(unsigned long long a,
                                                     unsigned long long b) {
    return b < a ? b : a;
}
__device__ __forceinline__ unsigned long long umax64(unsigned long long a,
                                                     unsigned long long b) {
    return a < b ? b : a;
}

static __device__ __forceinline__ uint32_t smem_u32(const void* p) {
    uint32_t a;
    asm("{ .reg .u64 t; cvta.to.shared.u64 t, %1; cvt.u32.u64 %0, t; }"
        : "=r"(a) : "l"(p));
    return a;
}

// mma.sync bf16 (sm_80+, valid at .target sm_100)
__device__ __forceinline__ void mma_bf16(float* d, const uint32_t* a,
                                         const uint32_t* b) {
    asm volatile(
        "mma.sync.aligned.m16n8k16.row.col.f32.bf16.bf16.f32 "
        "{%0,%1,%2,%3}, {%4,%5,%6,%7}, {%8,%9}, {%0,%1,%2,%3};"
        : "+f"(d[0]), "+f"(d[1]), "+f"(d[2]), "+f"(d[3])
        : "r"(a[0]), "r"(a[1]), "r"(a[2]), "r"(a[3]), "r"(b[0]), "r"(b[1]));
}
__device__ __forceinline__ void ldm_x4(uint32_t* r, uint32_t addr) {
    asm volatile(
        "ldmatrix.sync.aligned.m8n8.x4.shared.b16 {%0,%1,%2,%3}, [%4];"
        : "=r"(r[0]), "=r"(r[1]), "=r"(r[2]), "=r"(r[3]) : "r"(addr));
}

// ---------------------------------------------------------------------------
// Warp-cooperative bitonic sort of N = R*32 u64 keys (R regs/lane).
// ---------------------------------------------------------------------------
template <int R>
__device__ __forceinline__ void bitonic_sort(unsigned long long k[R], int lane) {
    const int N = R * 32;
#pragma unroll
    for (int kk = 2; kk <= N; kk <<= 1) {
#pragma unroll
        for (int j = kk >> 1; j > 0; j >>= 1) {
            if (j >= 32) {
                const int rj = j >> 5;
#pragma unroll
                for (int r = 0; r < R; ++r) {
                    if ((r & rj) == 0) {
                        const int r2 = r | rj;
                        const bool asc = (((r * 32) & kk) == 0);
                        const unsigned long long lo = umin64(k[r], k[r2]);
                        const unsigned long long hi = umax64(k[r], k[r2]);
                        k[r]  = asc ? lo : hi;
                        k[r2] = asc ? hi : lo;
                    }
                }
            } else {
#pragma unroll
                for (int r = 0; r < R; ++r) {
                    const unsigned long long other =
                        __shfl_xor_sync(0xffffffffu, k[r], j);
                    const int v = r * 32 + lane;
                    const bool asc     = ((v & kk) == 0);
                    const bool upper   = ((lane & j) != 0);
                    const bool keepMin = (asc != upper);
                    const unsigned long long mn = umin64(k[r], other);
                    const unsigned long long mx = umax64(k[r], other);
                    k[r] = keepMin ? mn : mx;
                }
            }
        }
    }
}

// ---------------------------------------------------------------------------
// Kernel 1: xw1[n][j] = sum_f x[n][f] * W1[f][j]   (f < 64)   [unchanged]
// ---------------------------------------------------------------------------
__global__ void __launch_bounds__(128) k_xw1(const float* __restrict__ x,
                                             const float* __restrict__ W1) {
    __shared__ float xs[8 * DIN];
    const int p0 = blockIdx.x * 8;
    const int tid = threadIdx.x;
    for (int i = tid; i < 8 * DIN; i += 128) xs[i] = x[p0 * DIN + i];
    __syncthreads();

    float acc[8];
#pragma unroll
    for (int p = 0; p < 8; ++p) acc[p] = 0.f;
#pragma unroll
    for (int f = 0; f < DIN; ++f) {
        float w = W1[f * H1DIM + tid];
#pragma unroll
        for (int p = 0; p < 8; ++p) acc[p] = fmaf(xs[p * DIN + f], w, acc[p]);
    }
#pragma unroll
    for (int p = 0; p < 8; ++p) g_xw1[(p0 + p) * H1DIM + tid] = acc[p];
}

// ---------------------------------------------------------------------------
// Kernel 1b: pack W2 into per-lane mma.sync B-fragments (bf16 hi/lo).
// For fragment (hl, wid, kt, t, h, lane):
//   k = kt*16 + (lane&3)*2 + 8*h ; n = wid*32 + t*8 + (lane>>2)
//   value = pack_bf16x2(part(W2[k][n]), part(W2[k+1][n]))
// ---------------------------------------------------------------------------
__global__ void __launch_bounds__(256) k_w2frag(const float* __restrict__ W2) {
    const int idx  = blockIdx.x * 256 + threadIdx.x;   // 0..32767
    const int lane = idx & 31;
    const int h    = (idx >> 5) & 1;
    const int t    = (idx >> 6) & 3;
    const int kt   = (idx >> 8) & 7;
    const int w    = (idx >> 11) & 7;
    const int hl   = (idx >> 14) & 1;

    const int k = kt * 16 + (lane & 3) * 2 + 8 * h;
    const int n = w * 32 + t * 8 + (lane >> 2);

    const float v0 = W2[k * H2DIM + n];
    const float v1 = W2[(k + 1) * H2DIM + n];
    __nv_bfloat16 p0, p1;
    if (hl == 0) {
        p0 = __float2bfloat16(v0);
        p1 = __float2bfloat16(v1);
    } else {
        const __nv_bfloat16 h0 = __float2bfloat16(v0);
        const __nv_bfloat16 h1 = __float2bfloat16(v1);
        p0 = __float2bfloat16(v0 - __bfloat162float(h0));
        p1 = __float2bfloat16(v1 - __bfloat162float(h1));
    }
    unsigned short u0, u1;
    memcpy(&u0, &p0, 2);
    memcpy(&u1, &p1, 2);
    g_w2frag[idx] = (uint32_t)u0 | ((uint32_t)u1 << 16);
}

// ---------------------------------------------------------------------------
// Kernel 2: KNN v3 (proven R5 version, unchanged).
// ---------------------------------------------------------------------------
#define SPB2 16
#define CAP  256

__global__ void __launch_bounds__(256) k_knn(const float* __restrict__ pos) {
    extern __shared__ float sm[];
    float* px = sm;
    float* py = sm + NP;
    float* pz = sm + 2 * NP;
    unsigned long long* lists = (unsigned long long*)(sm + 3 * NP); // [16][CAP]
    unsigned long long* warpT = lists + SPB2 * CAP;                 // [16][8]
    int* s_cnt = (int*)(warpT + SPB2 * 8);                          // [16]

    const int tid  = threadIdx.x;
    const int lane = tid & 31;
    const int wid  = tid >> 5;
    const int blk  = blockIdx.x;
    const int b    = blk / (NS / SPB2);
    const int grp  = blk % (NS / SPB2);

    for (int i = tid; i < NP; i += 256) {
        px[i] = pos[(b * NP + i) * 3 + 0];
        py[i] = pos[(b * NP + i) * 3 + 1];
        pz[i] = pos[(b * NP + i) * 3 + 2];
    }
    if (tid < SPB2) s_cnt[tid] = 0;
    __syncthreads();

    for (int si = 0; si < SPB2; ++si) {
        const int s_local = grp * SPB2 + si;
        const int c_local = s_local * STRIDE;
        const float ax = px[c_local], ay = py[c_local], az = pz[c_local];
        const float as2 = __fadd_rn(__fadd_rn(__fmul_rn(ax, ax), __fmul_rn(ay, ay)),
                                    __fmul_rn(az, az));

        unsigned long long keys[16];
#pragma unroll
        for (int t = 0; t < 16; ++t) {
            const int i = tid + t * 256;
            const float bx = px[i], by = py[i], bz = pz[i];
            const float bn2 = __fadd_rn(__fadd_rn(__fmul_rn(bx, bx), __fmul_rn(by, by)),
                                        __fmul_rn(bz, bz));
            const float dot = __fadd_rn(__fadd_rn(__fmul_rn(ax, bx), __fmul_rn(ay, by)),
                                        __fmul_rn(az, bz));
            const float d2  = __fadd_rn(__fadd_rn(as2, bn2), -__fmul_rn(2.0f, dot));
            unsigned u = __float_as_uint(d2);
            unsigned kk = (u & 0x80000000u) ? ~u : (u | 0x80000000u);
            keys[t] = (((unsigned long long)kk) << 32) | (unsigned)i;
        }
        unsigned long long lmin = keys[0];
#pragma unroll
        for (int t = 1; t < 16; ++t) lmin = umin64(lmin, keys[t]);

        unsigned long long tm[1] = { lmin };
        bitonic_sort<1>(tm, lane);
        const unsigned long long Tw = __shfl_sync(0xffffffffu, tm[0], 3);
        if (lane == 0) warpT[si * 8 + wid] = Tw;
        __syncthreads();

        unsigned long long T = warpT[si * 8 + 0];
#pragma unroll
        for (int q = 1; q < 8; ++q) T = umax64(T, warpT[si * 8 + q]);

        int cnt = 0;
#pragma unroll
        for (int t = 0; t < 16; ++t) cnt += (keys[t] <= T) ? 1 : 0;
        int base = atomicAdd(&s_cnt[si], cnt);
        unsigned long long* lst = lists + si * CAP;
#pragma unroll
        for (int t = 0; t < 16; ++t) {
            if (keys[t] <= T) {
                if (base < CAP) lst[base] = keys[t];
                ++base;
            }
        }
    }
    __syncthreads();

    for (int q = 0; q < 2; ++q) {
        const int si = wid + q * 8;
        int C = s_cnt[si];
        if (C > CAP) C = CAP;
        const int s_local = grp * SPB2 + si;
        const int sidx = b * NS + s_local;
        const unsigned long long* lst = lists + si * CAP;

        if (C <= 64) {
            unsigned long long k2[2];
#pragma unroll
            for (int r = 0; r < 2; ++r) {
                const int v = r * 32 + lane;
                k2[r] = (v < C) ? lst[v] : 0xffffffffffffffffull;
            }
            bitonic_sort<2>(k2, lane);
            g_nbr[sidx * KNN + lane] = (int)(unsigned)(k2[0] & 0xffffffffull);
        } else if (C <= 128) {
            unsigned long long k4[4];
#pragma unroll
            for (int r = 0; r < 4; ++r) {
                const int v = r * 32 + lane;
                k4[r] = (v < C) ? lst[v] : 0xffffffffffffffffull;
            }
            bitonic_sort<4>(k4, lane);
            g_nbr[sidx * KNN + lane] = (int)(unsigned)(k4[0] & 0xffffffffull);
        } else {
            unsigned long long k8[8];
#pragma unroll
            for (int r = 0; r < 8; ++r) {
                const int v = r * 32 + lane;
                k8[r] = (v < C) ? lst[v] : 0xffffffffffffffffull;
            }
            bitonic_sort<8>(k8, lane);
            g_nbr[sidx * KNN + lane] = (int)(unsigned)(k8[0] & 0xffffffffull);
        }
    }
}

// ---------------------------------------------------------------------------
// Kernel 3: MLP + max-pool via mma.sync split-bf16 (hh + hl + lh).
// One block = 4 samples, 8 warps. Warp w owns output cols [w*32, w*32+32).
// h1 (bf16 hi/lo) in smem with 136-element row stride (conflict-free
// ldmatrix); W2 B-fragments preloaded from g_w2frag into registers.
// ---------------------------------------------------------------------------
#define ROWSTRIDE 136                       // bf16 elements per h1 row
#define H1_BYTES  (4 * 32 * ROWSTRIDE * 2)  // 34816 per hi/lo array
#define SM_DYN    (2 * H1_BYTES)            // 69632

__global__ void __launch_bounds__(256, 1) k_mlp(const float* __restrict__ pos,
                                                const float* __restrict__ W1,
                                                const float* __restrict__ b1,
                                                const float* __restrict__ b2,
                                                float* __restrict__ out,
                                                int write_extras) {
    extern __shared__ __align__(16) char dyn[];
    __nv_bfloat16* h1hi = (__nv_bfloat16*)dyn;
    __nv_bfloat16* h1lo = (__nv_bfloat16*)(dyn + H1_BYTES);

    __shared__ float w1r[3][H1DIM];
    __shared__ float b1s[H1DIM];
    __shared__ float b2s[H2DIM];
    __shared__ float npx[128], npy[128], npz[128];   // [sample*32 + k]
    __shared__ int   gix[128];
    __shared__ float psmp[4][3];

    const int tid  = threadIdx.x;
    const int lane = tid & 31;
    const int wid  = tid >> 5;
    const int blk  = blockIdx.x;          // NSAMP/4 = 2048

    // ---- B-fragments: 64 hi + 64 lo u32 per thread, coalesced LDG ----
    uint32_t bhi[8][4][2], blo[8][4][2];
    {
        const uint32_t* fb = g_w2frag + wid * 2048 + lane;
#pragma unroll
        for (int u = 0; u < 64; ++u) {
            const int kt = u >> 3, t = (u >> 1) & 3, h = u & 1;
            bhi[kt][t][h] = fb[u * 32];
            blo[kt][t][h] = fb[16384 + u * 32];
        }
    }

    if (tid < H1DIM) {
        w1r[0][tid] = W1[64 * H1DIM + tid];
        w1r[1][tid] = W1[65 * H1DIM + tid];
        w1r[2][tid] = W1[66 * H1DIM + tid];
        b1s[tid]    = b1[tid];
    }
    b2s[tid] = b2[tid];

    // Neighbor metadata for all 4 samples
    if (tid < 128) {
        const int si = tid >> 5;
        const int s  = blk * 4 + si;
        const int b  = s >> 10;
        const int nl = g_nbr[s * KNN + (tid & 31)];
        const int g  = b * NP + nl;
        gix[tid] = g;
        npx[tid] = pos[3 * g];
        npy[tid] = pos[3 * g + 1];
        npz[tid] = pos[3 * g + 2];
    }
    // BUGFIX (R8 -> R9): was `tid < 12`, which never initialized psmp[3][*],
    // leaving sample 3 of every block with a garbage center position.
    if (tid < 16) {
        const int si = tid >> 2, c = tid & 3;
        if (c < 3) {
            const int s = blk * 4 + si;
            const int b = s >> 10;
            const int p = b * NP + (s & (NS - 1)) * STRIDE;
            psmp[si][c] = pos[3 * p + c];
        }
    }
    __syncthreads();

    // ---- h1 production: fp32 -> bf16 hi/lo into padded smem rows ----
    const int j    = tid & 127;           // hidden channel
    const int half = tid >> 7;            // neighbor parity
#pragma unroll
    for (int si = 0; si < 4; ++si) {
        const float psx = psmp[si][0], psy = psmp[si][1], psz = psmp[si][2];
#pragma unroll
        for (int kk = 0; kk < 16; ++kk) {
            const int k = kk * 2 + half;
            const int g = gix[si * 32 + k];
            float rx = npx[si * 32 + k] - psx;
            float ry = npy[si * 32 + k] - psy;
            float rz = npz[si * 32 + k] - psz;
            float v = g_xw1[g * H1DIM + j];
            v = fmaf(rx, w1r[0][j], v);
            v = fmaf(ry, w1r[1][j], v);
            v = fmaf(rz, w1r[2][j], v);
            v += b1s[j];
            v = fmaxf(v, 0.f);
            const __nv_bfloat16 hi = __float2bfloat16(v);
            const __nv_bfloat16 lo = __float2bfloat16(v - __bfloat162float(hi));
            const int off = (si * 32 + k) * ROWSTRIDE + j;
            h1hi[off] = hi;
            h1lo[off] = lo;
        }
    }
    __syncthreads();

    // ---- per-sample GEMM + max-pool (no further syncs; h1 read-only) ----
    const uint32_t h1hi_u = smem_u32(h1hi);
    const uint32_t h1lo_u = smem_u32(h1lo);
    const int lrow = lane & 15;
    const int lcol = (lane >> 4) & 1;

    for (int s4 = 0; s4 < 4; ++s4) {
        float acc[2][4][4];
#pragma unroll
        for (int mt = 0; mt < 2; ++mt)
#pragma unroll
            for (int nt = 0; nt < 4; ++nt)
#pragma unroll
                for (int e = 0; e < 4; ++e) acc[mt][nt][e] = 0.f;

#pragma unroll
        for (int kt = 0; kt < 8; ++kt) {
            uint32_t ahi[2][4], alo[2][4];
#pragma unroll
            for (int mt = 0; mt < 2; ++mt) {
                const uint32_t byteoff =
                    (uint32_t)(((s4 * 32 + mt * 16 + lrow) * ROWSTRIDE +
                                kt * 16 + lcol * 8) * 2);
                ldm_x4(ahi[mt], h1hi_u + byteoff);
                ldm_x4(alo[mt], h1lo_u + byteoff);
            }
#pragma unroll
            for (int mt = 0; mt < 2; ++mt)
#pragma unroll
                for (int nt = 0; nt < 4; ++nt) {
                    mma_bf16(acc[mt][nt], ahi[mt], bhi[kt][nt]);
                    mma_bf16(acc[mt][nt], ahi[mt], blo[kt][nt]);
                    mma_bf16(acc[mt][nt], alo[mt], bhi[kt][nt]);
                }
        }

        // Epilogue: max over 32 neighbor rows, then bias + relu, store.
        const int s = blk * 4 + s4;
#pragma unroll
        for (int nt = 0; nt < 4; ++nt)
#pragma unroll
            for (int par = 0; par < 2; ++par) {
                float m = fmaxf(fmaxf(acc[0][nt][par], acc[0][nt][par + 2]),
                                fmaxf(acc[1][nt][par], acc[1][nt][par + 2]));
                m = fmaxf(m, __shfl_xor_sync(0xffffffffu, m, 4));
                m = fmaxf(m, __shfl_xor_sync(0xffffffffu, m, 8));
                m = fmaxf(m, __shfl_xor_sync(0xffffffffu, m, 16));
                if (lane < 4) {
                    const int c = wid * 32 + nt * 8 + (lane & 3) * 2 + par;
                    out[XOUT_OFF + s * H2DIM + c] = fmaxf(m + b2s[c], 0.f);
                }
            }
    }

    if (write_extras) {
#pragma unroll
        for (int si = 0; si < 4; ++si) {
            const int s = blk * 4 + si;
            const int b = s >> 10;
            const int p = b * NP + (s & (NS - 1)) * STRIDE;
            if (tid < 3)  out[POS_OFF + s * 3 + tid] = psmp[si][tid];
            if (tid == 3) out[BATCH_OFF + s] = (float)b;
            if (tid == 4) out[IDX_OFF + s]   = (float)p;
        }
    }
}

// ---------------------------------------------------------------------------
extern "C" void kernel_launch(void* const* d_in, const int* in_sizes, int n_in,
                              void* d_out, int out_size) {
    const float* x   = (const float*)d_in[0];
    const float* pos = (const float*)d_in[1];
    const float* W1  = (const float*)d_in[3];
    const float* b1  = (const float*)d_in[4];
    const float* W2  = (const float*)d_in[5];
    const float* b2  = (const float*)d_in[6];
    float* out = (float*)d_out;

    const int write_extras = (out_size >= TOTAL_OUT) ? 1 : 0;

    k_xw1<<<NPTS / 8, 128>>>(x, W1);
    k_w2frag<<<128, 256>>>(W2);

    const int smem2 = 3 * NP * (int)sizeof(float)
                    + SPB2 * CAP * (int)sizeof(unsigned long long)
                    + SPB2 * 8 * (int)sizeof(unsigned long long)
                    + SPB2 * (int)sizeof(int);
    cudaFuncSetAttribute(k_knn, cudaFuncAttributeMaxDynamicSharedMemorySize, smem2);
    k_knn<<<BATCHES * (NS / SPB2), 256, smem2>>>(pos);

    cudaFuncSetAttribute(k_mlp, cudaFuncAttributeMaxDynamicSharedMemorySize, SM_DYN);
    k_mlp<<<NSAMP / 4, 256, SM_DYN>>>(pos, W1, b1, b2, out, write_extras);
}

// round 11
// speedup vs baseline: 5.5536x; 1.5722x over previous
#include <cuda_runtime.h>
#include <cuda_fp16.h>
#include <cstdint>

// Problem constants (from reference)
#define BATCHES 8
#define NP 4096
#define STRIDE 4
#define KNN 32
#define NS (NP / STRIDE)          // 1024 samples per batch
#define NSAMP (BATCHES * NS)      // 8192
#define NPTS (BATCHES * NP)       // 32768
#define DIN 64
#define H1DIM 128
#define H2DIM 256

// Output layout (float32 concat of the reference tuple)
#define XOUT_OFF   0
#define POS_OFF    (NSAMP * H2DIM)                 // 2097152
#define BATCH_OFF  (POS_OFF + NSAMP * 3)           // 2121728
#define IDX_OFF    (BATCH_OFF + NSAMP)             // 2129920
#define TOTAL_OUT  (IDX_OFF + NSAMP)               // 2138112

// Scratch (static __device__ arrays: no allocation)
__device__ float g_xw1[NPTS * H1DIM];     // 16 MB: x @ W1[:64]
__device__ int   g_nbr[NSAMP * KNN];      // 1 MB : local neighbor indices
// W2 packed as per-lane mma.sync B-fragments, fp16 hi only:
// flat index = wid*2048 + kt*256 + t*64 + h*32 + lane
__device__ uint32_t g_w2frag[16384];      // 64 KB

__device__ __forceinline__ unsigned long long umin64(unsigned long long a,
                                                     unsigned long long b) {
    return b < a ? b : a;
}
__device__ __forceinline__ unsigned long long umax64(unsigned long long a,
                                                     unsigned long long b) {
    return a < b ? b : a;
}

static __device__ __forceinline__ uint32_t smem_u32(const void* p) {
    uint32_t a;
    asm("{ .reg .u64 t; cvta.to.shared.u64 t, %1; cvt.u32.u64 %0, t; }"
        : "=r"(a) : "l"(p));
    return a;
}

// mma.sync fp16 (sm_80+, valid at .target sm_100)
__device__ __forceinline__ void mma_f16(float* d, const uint32_t* a,
                                        const uint32_t* b) {
    asm volatile(
        "mma.sync.aligned.m16n8k16.row.col.f32.f16.f16.f32 "
        "{%0,%1,%2,%3}, {%4,%5,%6,%7}, {%8,%9}, {%0,%1,%2,%3};"
        : "+f"(d[0]), "+f"(d[1]), "+f"(d[2]), "+f"(d[3])
        : "r"(a[0]), "r"(a[1]), "r"(a[2]), "r"(a[3]), "r"(b[0]), "r"(b[1]));
}
__device__ __forceinline__ void ldm_x4(uint32_t* r, uint32_t addr) {
    asm volatile(
        "ldmatrix.sync.aligned.m8n8.x4.shared.b16 {%0,%1,%2,%3}, [%4];"
        : "=r"(r[0]), "=r"(r[1]), "=r"(r[2]), "=r"(r[3]) : "r"(addr));
}

// ---------------------------------------------------------------------------
// Warp-cooperative bitonic sort of N = R*32 u64 keys (R regs/lane).
// ---------------------------------------------------------------------------
template <int R>
__device__ __forceinline__ void bitonic_sort(unsigned long long k[R], int lane) {
    const int N = R * 32;
#pragma unroll
    for (int kk = 2; kk <= N; kk <<= 1) {
#pragma unroll
        for (int j = kk >> 1; j > 0; j >>= 1) {
            if (j >= 32) {
                const int rj = j >> 5;
#pragma unroll
                for (int r = 0; r < R; ++r) {
                    if ((r & rj) == 0) {
                        const int r2 = r | rj;
                        const bool asc = (((r * 32) & kk) == 0);
                        const unsigned long long lo = umin64(k[r], k[r2]);
                        const unsigned long long hi = umax64(k[r], k[r2]);
                        k[r]  = asc ? lo : hi;
                        k[r2] = asc ? hi : lo;
                    }
                }
            } else {
#pragma unroll
                for (int r = 0; r < R; ++r) {
                    const unsigned long long other =
                        __shfl_xor_sync(0xffffffffu, k[r], j);
                    const int v = r * 32 + lane;
                    const bool asc     = ((v & kk) == 0);
                    const bool upper   = ((lane & j) != 0);
                    const bool keepMin = (asc != upper);
                    const unsigned long long mn = umin64(k[r], other);
                    const unsigned long long mx = umax64(k[r], other);
                    k[r] = keepMin ? mn : mx;
                }
            }
        }
    }
}

// ---------------------------------------------------------------------------
// Kernel 1: xw1[n][j] = sum_f x[n][f] * W1[f][j]   (f < 64)   [unchanged]
// ---------------------------------------------------------------------------
__global__ void __launch_bounds__(128) k_xw1(const float* __restrict__ x,
                                             const float* __restrict__ W1) {
    __shared__ float xs[8 * DIN];
    const int p0 = blockIdx.x * 8;
    const int tid = threadIdx.x;
    for (int i = tid; i < 8 * DIN; i += 128) xs[i] = x[p0 * DIN + i];
    __syncthreads();

    float acc[8];
#pragma unroll
    for (int p = 0; p < 8; ++p) acc[p] = 0.f;
#pragma unroll
    for (int f = 0; f < DIN; ++f) {
        float w = W1[f * H1DIM + tid];
#pragma unroll
        for (int p = 0; p < 8; ++p) acc[p] = fmaf(xs[p * DIN + f], w, acc[p]);
    }
#pragma unroll
    for (int p = 0; p < 8; ++p) g_xw1[(p0 + p) * H1DIM + tid] = acc[p];
}

// ---------------------------------------------------------------------------
// Kernel 1b: pack W2 into per-lane mma.sync B-fragments (fp16 hi only).
// For fragment (wid, kt, t, h, lane):
//   k = kt*16 + (lane&3)*2 + 8*h ; n = wid*32 + t*8 + (lane>>2)
// ---------------------------------------------------------------------------
__global__ void __launch_bounds__(256) k_w2frag(const float* __restrict__ W2) {
    const int idx  = blockIdx.x * 256 + threadIdx.x;   // 0..16383
    const int lane = idx & 31;
    const int h    = (idx >> 5) & 1;
    const int t    = (idx >> 6) & 3;
    const int kt   = (idx >> 8) & 7;
    const int w    = (idx >> 11) & 7;

    const int k = kt * 16 + (lane & 3) * 2 + 8 * h;
    const int n = w * 32 + t * 8 + (lane >> 2);

    const __half p0 = __float2half_rn(W2[k * H2DIM + n]);
    const __half p1 = __float2half_rn(W2[(k + 1) * H2DIM + n]);
    unsigned short u0, u1;
    memcpy(&u0, &p0, 2);
    memcpy(&u1, &p1, 2);
    g_w2frag[idx] = (uint32_t)u0 | ((uint32_t)u1 << 16);
}

// ---------------------------------------------------------------------------
// Kernel 2: KNN v3 (proven R5 version, unchanged).
// ---------------------------------------------------------------------------
#define SPB2 16
#define CAP  256

__global__ void __launch_bounds__(256) k_knn(const float* __restrict__ pos) {
    extern __shared__ float sm[];
    float* px = sm;
    float* py = sm + NP;
    float* pz = sm + 2 * NP;
    unsigned long long* lists = (unsigned long long*)(sm + 3 * NP); // [16][CAP]
    unsigned long long* warpT = lists + SPB2 * CAP;                 // [16][8]
    int* s_cnt = (int*)(warpT + SPB2 * 8);                          // [16]

    const int tid  = threadIdx.x;
    const int lane = tid & 31;
    const int wid  = tid >> 5;
    const int blk  = blockIdx.x;
    const int b    = blk / (NS / SPB2);
    const int grp  = blk % (NS / SPB2);

    for (int i = tid; i < NP; i += 256) {
        px[i] = pos[(b * NP + i) * 3 + 0];
        py[i] = pos[(b * NP + i) * 3 + 1];
        pz[i] = pos[(b * NP + i) * 3 + 2];
    }
    if (tid < SPB2) s_cnt[tid] = 0;
    __syncthreads();

    for (int si = 0; si < SPB2; ++si) {
        const int s_local = grp * SPB2 + si;
        const int c_local = s_local * STRIDE;
        const float ax = px[c_local], ay = py[c_local], az = pz[c_local];
        const float as2 = __fadd_rn(__fadd_rn(__fmul_rn(ax, ax), __fmul_rn(ay, ay)),
                                    __fmul_rn(az, az));

        unsigned long long keys[16];
#pragma unroll
        for (int t = 0; t < 16; ++t) {
            const int i = tid + t * 256;
            const float bx = px[i], by = py[i], bz = pz[i];
            const float bn2 = __fadd_rn(__fadd_rn(__fmul_rn(bx, bx), __fmul_rn(by, by)),
                                        __fmul_rn(bz, bz));
            const float dot = __fadd_rn(__fadd_rn(__fmul_rn(ax, bx), __fmul_rn(ay, by)),
                                        __fmul_rn(az, bz));
            const float d2  = __fadd_rn(__fadd_rn(as2, bn2), -__fmul_rn(2.0f, dot));
            unsigned u = __float_as_uint(d2);
            unsigned kk = (u & 0x80000000u) ? ~u : (u | 0x80000000u);
            keys[t] = (((unsigned long long)kk) << 32) | (unsigned)i;
        }
        unsigned long long lmin = keys[0];
#pragma unroll
        for (int t = 1; t < 16; ++t) lmin = umin64(lmin, keys[t]);

        unsigned long long tm[1] = { lmin };
        bitonic_sort<1>(tm, lane);
        const unsigned long long Tw = __shfl_sync(0xffffffffu, tm[0], 3);
        if (lane == 0) warpT[si * 8 + wid] = Tw;
        __syncthreads();

        unsigned long long T = warpT[si * 8 + 0];
#pragma unroll
        for (int q = 1; q < 8; ++q) T = umax64(T, warpT[si * 8 + q]);

        int cnt = 0;
#pragma unroll
        for (int t = 0; t < 16; ++t) cnt += (keys[t] <= T) ? 1 : 0;
        int base = atomicAdd(&s_cnt[si], cnt);
        unsigned long long* lst = lists + si * CAP;
#pragma unroll
        for (int t = 0; t < 16; ++t) {
            if (keys[t] <= T) {
                if (base < CAP) lst[base] = keys[t];
                ++base;
            }
        }
    }
    __syncthreads();

    for (int q = 0; q < 2; ++q) {
        const int si = wid + q * 8;
        int C = s_cnt[si];
        if (C > CAP) C = CAP;
        const int s_local = grp * SPB2 + si;
        const int sidx = b * NS + s_local;
        const unsigned long long* lst = lists + si * CAP;

        if (C <= 64) {
            unsigned long long k2[2];
#pragma unroll
            for (int r = 0; r < 2; ++r) {
                const int v = r * 32 + lane;
                k2[r] = (v < C) ? lst[v] : 0xffffffffffffffffull;
            }
            bitonic_sort<2>(k2, lane);
            g_nbr[sidx * KNN + lane] = (int)(unsigned)(k2[0] & 0xffffffffull);
        } else if (C <= 128) {
            unsigned long long k4[4];
#pragma unroll
            for (int r = 0; r < 4; ++r) {
                const int v = r * 32 + lane;
                k4[r] = (v < C) ? lst[v] : 0xffffffffffffffffull;
            }
            bitonic_sort<4>(k4, lane);
            g_nbr[sidx * KNN + lane] = (int)(unsigned)(k4[0] & 0xffffffffull);
        } else {
            unsigned long long k8[8];
#pragma unroll
            for (int r = 0; r < 8; ++r) {
                const int v = r * 32 + lane;
                k8[r] = (v < C) ? lst[v] : 0xffffffffffffffffull;
            }
            bitonic_sort<8>(k8, lane);
            g_nbr[sidx * KNN + lane] = (int)(unsigned)(k8[0] & 0xffffffffull);
        }
    }
}

// ---------------------------------------------------------------------------
// Kernel 3: MLP + max-pool via mma.sync fp16, asymmetric split:
//   A = h1 in fp16 hi+lo (exact to ~2^-22), B = W2 fp16 hi only.
//   acc = ahi*b + alo*b   (2 mma per tile instead of 3)
// B-frags: 64 regs/thread -> __launch_bounds__(256,2) gives 2 blocks/SM.
// ---------------------------------------------------------------------------
#define ROWSTRIDE 136                       // fp16 elements per h1 row
#define H1_BYTES  (4 * 32 * ROWSTRIDE * 2)  // 34816 per hi/lo array
#define SM_DYN    (2 * H1_BYTES)            // 69632

__global__ void __launch_bounds__(256, 2) k_mlp(const float* __restrict__ pos,
                                                const float* __restrict__ W1,
                                                const float* __restrict__ b1,
                                                const float* __restrict__ b2,
                                                float* __restrict__ out,
                                                int write_extras) {
    extern __shared__ __align__(16) char dyn[];
    __half* h1hi = (__half*)dyn;
    __half* h1lo = (__half*)(dyn + H1_BYTES);

    __shared__ float w1r[3][H1DIM];
    __shared__ float b1s[H1DIM];
    __shared__ float b2s[H2DIM];
    __shared__ float npx[128], npy[128], npz[128];   // [sample*32 + k]
    __shared__ int   gix[128];
    __shared__ float psmp[4][3];

    const int tid  = threadIdx.x;
    const int lane = tid & 31;
    const int wid  = tid >> 5;
    const int blk  = blockIdx.x;          // NSAMP/4 = 2048

    // ---- B-fragments: 64 u32 per thread, coalesced LDG ----
    uint32_t bfr[8][4][2];
    {
        const uint32_t* fb = g_w2frag + wid * 2048 + lane;
#pragma unroll
        for (int u = 0; u < 64; ++u) {
            const int kt = u >> 3, t = (u >> 1) & 3, h = u & 1;
            bfr[kt][t][h] = fb[u * 32];
        }
    }

    if (tid < H1DIM) {
        w1r[0][tid] = W1[64 * H1DIM + tid];
        w1r[1][tid] = W1[65 * H1DIM + tid];
        w1r[2][tid] = W1[66 * H1DIM + tid];
        b1s[tid]    = b1[tid];
    }
    b2s[tid] = b2[tid];

    // Neighbor metadata for all 4 samples
    if (tid < 128) {
        const int si = tid >> 5;
        const int s  = blk * 4 + si;
        const int b  = s >> 10;
        const int nl = g_nbr[s * KNN + (tid & 31)];
        const int g  = b * NP + nl;
        gix[tid] = g;
        npx[tid] = pos[3 * g];
        npy[tid] = pos[3 * g + 1];
        npz[tid] = pos[3 * g + 2];
    }
    if (tid < 16) {                        // covers psmp[0..3]
        const int si = tid >> 2, c = tid & 3;
        if (c < 3) {
            const int s = blk * 4 + si;
            const int b = s >> 10;
            const int p = b * NP + (s & (NS - 1)) * STRIDE;
            psmp[si][c] = pos[3 * p + c];
        }
    }
    __syncthreads();

    // ---- h1 production: fp32 -> fp16 hi/lo into padded smem rows ----
    const int j    = tid & 127;           // hidden channel
    const int half = tid >> 7;            // neighbor parity
#pragma unroll
    for (int si = 0; si < 4; ++si) {
        const float psx = psmp[si][0], psy = psmp[si][1], psz = psmp[si][2];
#pragma unroll
        for (int kk = 0; kk < 16; ++kk) {
            const int k = kk * 2 + half;
            const int g = gix[si * 32 + k];
            float rx = npx[si * 32 + k] - psx;
            float ry = npy[si * 32 + k] - psy;
            float rz = npz[si * 32 + k] - psz;
            float v = g_xw1[g * H1DIM + j];
            v = fmaf(rx, w1r[0][j], v);
            v = fmaf(ry, w1r[1][j], v);
            v = fmaf(rz, w1r[2][j], v);
            v += b1s[j];
            v = fmaxf(v, 0.f);
            const __half hi = __float2half_rn(v);
            const __half lo = __float2half_rn(v - __half2float(hi));
            const int off = (si * 32 + k) * ROWSTRIDE + j;
            h1hi[off] = hi;
            h1lo[off] = lo;
        }
    }
    __syncthreads();

    // ---- per-sample GEMM + max-pool (no further syncs; h1 read-only) ----
    const uint32_t h1hi_u = smem_u32(h1hi);
    const uint32_t h1lo_u = smem_u32(h1lo);
    const int lrow = lane & 15;
    const int lcol = (lane >> 4) & 1;

    for (int s4 = 0; s4 < 4; ++s4) {
        float acc[2][4][4];
#pragma unroll
        for (int mt = 0; mt < 2; ++mt)
#pragma unroll
            for (int nt = 0; nt < 4; ++nt)
#pragma unroll
                for (int e = 0; e < 4; ++e) acc[mt][nt][e] = 0.f;

#pragma unroll
        for (int kt = 0; kt < 8; ++kt) {
            uint32_t ahi[2][4], alo[2][4];
#pragma unroll
            for (int mt = 0; mt < 2; ++mt) {
                const uint32_t byteoff =
                    (uint32_t)(((s4 * 32 + mt * 16 + lrow) * ROWSTRIDE +
                                kt * 16 + lcol * 8) * 2);
                ldm_x4(ahi[mt], h1hi_u + byteoff);
                ldm_x4(alo[mt], h1lo_u + byteoff);
            }
#pragma unroll
            for (int mt = 0; mt < 2; ++mt)
#pragma unroll
                for (int nt = 0; nt < 4; ++nt) {
                    mma_f16(acc[mt][nt], ahi[mt], bfr[kt][nt]);
                    mma_f16(acc[mt][nt], alo[mt], bfr[kt][nt]);
                }
        }

        // Epilogue: max over 32 neighbor rows, then bias + relu, store.
        const int s = blk * 4 + s4;
#pragma unroll
        for (int nt = 0; nt < 4; ++nt)
#pragma unroll
            for (int par = 0; par < 2; ++par) {
                float m = fmaxf(fmaxf(acc[0][nt][par], acc[0][nt][par + 2]),
                                fmaxf(acc[1][nt][par], acc[1][nt][par + 2]));
                m = fmaxf(m, __shfl_xor_sync(0xffffffffu, m, 4));
                m = fmaxf(m, __shfl_xor_sync(0xffffffffu, m, 8));
                m = fmaxf(m, __shfl_xor_sync(0xffffffffu, m, 16));
                if (lane < 4) {
                    const int c = wid * 32 + nt * 8 + (lane & 3) * 2 + par;
                    out[XOUT_OFF + s * H2DIM + c] = fmaxf(m + b2s[c], 0.f);
                }
            }
    }

    if (write_extras) {
#pragma unroll
        for (int si = 0; si < 4; ++si) {
            const int s = blk * 4 + si;
            const int b = s >> 10;
            const int p = b * NP + (s & (NS - 1)) * STRIDE;
            if (tid < 3)  out[POS_OFF + s * 3 + tid] = psmp[si][tid];
            if (tid == 3) out[BATCH_OFF + s] = (float)b;
            if (tid == 4) out[IDX_OFF + s]   = (float)p;
        }
    }
}

// ---------------------------------------------------------------------------
extern "C" void kernel_launch(void* const* d_in, const int* in_sizes, int n_in,
                              void* d_out, int out_size) {
    const float* x   = (const float*)d_in[0];
    const float* pos = (const float*)d_in[1];
    const float* W1  = (const float*)d_in[3];
    const float* b1  = (const float*)d_in[4];
    const float* W2  = (const float*)d_in[5];
    const float* b2  = (const float*)d_in[6];
    float* out = (float*)d_out;

    const int write_extras = (out_size >= TOTAL_OUT) ? 1 : 0;

    k_xw1<<<NPTS / 8, 128>>>(x, W1);
    k_w2frag<<<64, 256>>>(W2);

    const int smem2 = 3 * NP * (int)sizeof(float)
                    + SPB2 * CAP * (int)sizeof(unsigned long long)
                    + SPB2 * 8 * (int)sizeof(unsigned long long)
                    + SPB2 * (int)sizeof(int);
    cudaFuncSetAttribute(k_knn, cudaFuncAttributeMaxDynamicSharedMemorySize, smem2);
    k_knn<<<BATCHES * (NS / SPB2), 256, smem2>>>(pos);

    cudaFuncSetAttribute(k_mlp, cudaFuncAttributeMaxDynamicSharedMemorySize, SM_DYN);
    k_mlp<<<NSAMP / 4, 256, SM_DYN>>>(pos, W1, b1, b2, out, write_extras);
}

// round 12
// speedup vs baseline: 6.1368x; 1.1050x over previous
#include <cuda_runtime.h>
#include <cuda_fp16.h>
#include <cstdint>

// Problem constants (from reference)
#define BATCHES 8
#define NP 4096
#define STRIDE 4
#define KNN 32
#define NS (NP / STRIDE)          // 1024 samples per batch
#define NSAMP (BATCHES * NS)      // 8192
#define NPTS (BATCHES * NP)       // 32768
#define DIN 64
#define H1DIM 128
#define H2DIM 256

// Output layout (float32 concat of the reference tuple)
#define XOUT_OFF   0
#define POS_OFF    (NSAMP * H2DIM)                 // 2097152
#define BATCH_OFF  (POS_OFF + NSAMP * 3)           // 2121728
#define IDX_OFF    (BATCH_OFF + NSAMP)             // 2129920
#define TOTAL_OUT  (IDX_OFF + NSAMP)               // 2138112

// Scratch (static __device__ arrays: no allocation)
__device__ float g_xw1[NPTS * H1DIM];     // 16 MB: x @ W1[:64]
__device__ int   g_nbr[NSAMP * KNN];      // 1 MB : local neighbor indices
// W2 packed as per-lane mma.sync B-fragments, fp16:
// flat index = wid*2048 + kt*256 + t*64 + h*32 + lane
__device__ uint32_t g_w2frag[16384];      // 64 KB

__device__ __forceinline__ unsigned long long umin64(unsigned long long a,
                                                     unsigned long long b) {
    return b < a ? b : a;
}
__device__ __forceinline__ unsigned long long umax64(unsigned long long a,
                                                     unsigned long long b) {
    return a < b ? b : a;
}

static __device__ __forceinline__ uint32_t smem_u32(const void* p) {
    uint32_t a;
    asm("{ .reg .u64 t; cvta.to.shared.u64 t, %1; cvt.u32.u64 %0, t; }"
        : "=r"(a) : "l"(p));
    return a;
}

// mma.sync fp16 (sm_80+, valid at .target sm_100)
__device__ __forceinline__ void mma_f16(float* d, const uint32_t* a,
                                        const uint32_t* b) {
    asm volatile(
        "mma.sync.aligned.m16n8k16.row.col.f32.f16.f16.f32 "
        "{%0,%1,%2,%3}, {%4,%5,%6,%7}, {%8,%9}, {%0,%1,%2,%3};"
        : "+f"(d[0]), "+f"(d[1]), "+f"(d[2]), "+f"(d[3])
        : "r"(a[0]), "r"(a[1]), "r"(a[2]), "r"(a[3]), "r"(b[0]), "r"(b[1]));
}
__device__ __forceinline__ void ldm_x4(uint32_t* r, uint32_t addr) {
    asm volatile(
        "ldmatrix.sync.aligned.m8n8.x4.shared.b16 {%0,%1,%2,%3}, [%4];"
        : "=r"(r[0]), "=r"(r[1]), "=r"(r[2]), "=r"(r[3]) : "r"(addr));
}

// ---------------------------------------------------------------------------
// Warp-cooperative bitonic sort of N = R*32 u64 keys (R regs/lane).
// ---------------------------------------------------------------------------
template <int R>
__device__ __forceinline__ void bitonic_sort(unsigned long long k[R], int lane) {
    const int N = R * 32;
#pragma unroll
    for (int kk = 2; kk <= N; kk <<= 1) {
#pragma unroll
        for (int j = kk >> 1; j > 0; j >>= 1) {
            if (j >= 32) {
                const int rj = j >> 5;
#pragma unroll
                for (int r = 0; r < R; ++r) {
                    if ((r & rj) == 0) {
                        const int r2 = r | rj;
                        const bool asc = (((r * 32) & kk) == 0);
                        const unsigned long long lo = umin64(k[r], k[r2]);
                        const unsigned long long hi = umax64(k[r], k[r2]);
                        k[r]  = asc ? lo : hi;
                        k[r2] = asc ? hi : lo;
                    }
                }
            } else {
#pragma unroll
                for (int r = 0; r < R; ++r) {
                    const unsigned long long other =
                        __shfl_xor_sync(0xffffffffu, k[r], j);
                    const int v = r * 32 + lane;
                    const bool asc     = ((v & kk) == 0);
                    const bool upper   = ((lane & j) != 0);
                    const bool keepMin = (asc != upper);
                    const unsigned long long mn = umin64(k[r], other);
                    const unsigned long long mx = umax64(k[r], other);
                    k[r] = keepMin ? mn : mx;
                }
            }
        }
    }
}

// ---------------------------------------------------------------------------
// Kernel 1: xw1[n][j] = sum_f x[n][f] * W1[f][j]   (f < 64)   [unchanged]
// ---------------------------------------------------------------------------
__global__ void __launch_bounds__(128) k_xw1(const float* __restrict__ x,
                                             const float* __restrict__ W1) {
    __shared__ float xs[8 * DIN];
    const int p0 = blockIdx.x * 8;
    const int tid = threadIdx.x;
    for (int i = tid; i < 8 * DIN; i += 128) xs[i] = x[p0 * DIN + i];
    __syncthreads();

    float acc[8];
#pragma unroll
    for (int p = 0; p < 8; ++p) acc[p] = 0.f;
#pragma unroll
    for (int f = 0; f < DIN; ++f) {
        float w = W1[f * H1DIM + tid];
#pragma unroll
        for (int p = 0; p < 8; ++p) acc[p] = fmaf(xs[p * DIN + f], w, acc[p]);
    }
#pragma unroll
    for (int p = 0; p < 8; ++p) g_xw1[(p0 + p) * H1DIM + tid] = acc[p];
}

// ---------------------------------------------------------------------------
// Kernel 1b: pack W2 into per-lane mma.sync B-fragments (fp16).
// For fragment (wid, kt, t, h, lane):
//   k = kt*16 + (lane&3)*2 + 8*h ; n = wid*32 + t*8 + (lane>>2)
// ---------------------------------------------------------------------------
__global__ void __launch_bounds__(256) k_w2frag(const float* __restrict__ W2) {
    const int idx  = blockIdx.x * 256 + threadIdx.x;   // 0..16383
    const int lane = idx & 31;
    const int h    = (idx >> 5) & 1;
    const int t    = (idx >> 6) & 3;
    const int kt   = (idx >> 8) & 7;
    const int w    = (idx >> 11) & 7;

    const int k = kt * 16 + (lane & 3) * 2 + 8 * h;
    const int n = w * 32 + t * 8 + (lane >> 2);

    const __half p0 = __float2half_rn(W2[k * H2DIM + n]);
    const __half p1 = __float2half_rn(W2[(k + 1) * H2DIM + n]);
    unsigned short u0, u1;
    memcpy(&u0, &p0, 2);
    memcpy(&u1, &p1, 2);
    g_w2frag[idx] = (uint32_t)u0 | ((uint32_t)u1 << 16);
}

// ---------------------------------------------------------------------------
// Kernel 2: KNN v3 (proven R5 version, unchanged).
// ---------------------------------------------------------------------------
#define SPB2 16
#define CAP  256

__global__ void __launch_bounds__(256) k_knn(const float* __restrict__ pos) {
    extern __shared__ float sm[];
    float* px = sm;
    float* py = sm + NP;
    float* pz = sm + 2 * NP;
    unsigned long long* lists = (unsigned long long*)(sm + 3 * NP); // [16][CAP]
    unsigned long long* warpT = lists + SPB2 * CAP;                 // [16][8]
    int* s_cnt = (int*)(warpT + SPB2 * 8);                          // [16]

    const int tid  = threadIdx.x;
    const int lane = tid & 31;
    const int wid  = tid >> 5;
    const int blk  = blockIdx.x;
    const int b    = blk / (NS / SPB2);
    const int grp  = blk % (NS / SPB2);

    for (int i = tid; i < NP; i += 256) {
        px[i] = pos[(b * NP + i) * 3 + 0];
        py[i] = pos[(b * NP + i) * 3 + 1];
        pz[i] = pos[(b * NP + i) * 3 + 2];
    }
    if (tid < SPB2) s_cnt[tid] = 0;
    __syncthreads();

    for (int si = 0; si < SPB2; ++si) {
        const int s_local = grp * SPB2 + si;
        const int c_local = s_local * STRIDE;
        const float ax = px[c_local], ay = py[c_local], az = pz[c_local];
        const float as2 = __fadd_rn(__fadd_rn(__fmul_rn(ax, ax), __fmul_rn(ay, ay)),
                                    __fmul_rn(az, az));

        unsigned long long keys[16];
#pragma unroll
        for (int t = 0; t < 16; ++t) {
            const int i = tid + t * 256;
            const float bx = px[i], by = py[i], bz = pz[i];
            const float bn2 = __fadd_rn(__fadd_rn(__fmul_rn(bx, bx), __fmul_rn(by, by)),
                                        __fmul_rn(bz, bz));
            const float dot = __fadd_rn(__fadd_rn(__fmul_rn(ax, bx), __fmul_rn(ay, by)),
                                        __fmul_rn(az, bz));
            const float d2  = __fadd_rn(__fadd_rn(as2, bn2), -__fmul_rn(2.0f, dot));
            unsigned u = __float_as_uint(d2);
            unsigned kk = (u & 0x80000000u) ? ~u : (u | 0x80000000u);
            keys[t] = (((unsigned long long)kk) << 32) | (unsigned)i;
        }
        unsigned long long lmin = keys[0];
#pragma unroll
        for (int t = 1; t < 16; ++t) lmin = umin64(lmin, keys[t]);

        unsigned long long tm[1] = { lmin };
        bitonic_sort<1>(tm, lane);
        const unsigned long long Tw = __shfl_sync(0xffffffffu, tm[0], 3);
        if (lane == 0) warpT[si * 8 + wid] = Tw;
        __syncthreads();

        unsigned long long T = warpT[si * 8 + 0];
#pragma unroll
        for (int q = 1; q < 8; ++q) T = umax64(T, warpT[si * 8 + q]);

        int cnt = 0;
#pragma unroll
        for (int t = 0; t < 16; ++t) cnt += (keys[t] <= T) ? 1 : 0;
        int base = atomicAdd(&s_cnt[si], cnt);
        unsigned long long* lst = lists + si * CAP;
#pragma unroll
        for (int t = 0; t < 16; ++t) {
            if (keys[t] <= T) {
                if (base < CAP) lst[base] = keys[t];
                ++base;
            }
        }
    }
    __syncthreads();

    for (int q = 0; q < 2; ++q) {
        const int si = wid + q * 8;
        int C = s_cnt[si];
        if (C > CAP) C = CAP;
        const int s_local = grp * SPB2 + si;
        const int sidx = b * NS + s_local;
        const unsigned long long* lst = lists + si * CAP;

        if (C <= 64) {
            unsigned long long k2[2];
#pragma unroll
            for (int r = 0; r < 2; ++r) {
                const int v = r * 32 + lane;
                k2[r] = (v < C) ? lst[v] : 0xffffffffffffffffull;
            }
            bitonic_sort<2>(k2, lane);
            g_nbr[sidx * KNN + lane] = (int)(unsigned)(k2[0] & 0xffffffffull);
        } else if (C <= 128) {
            unsigned long long k4[4];
#pragma unroll
            for (int r = 0; r < 4; ++r) {
                const int v = r * 32 + lane;
                k4[r] = (v < C) ? lst[v] : 0xffffffffffffffffull;
            }
            bitonic_sort<4>(k4, lane);
            g_nbr[sidx * KNN + lane] = (int)(unsigned)(k4[0] & 0xffffffffull);
        } else {
            unsigned long long k8[8];
#pragma unroll
            for (int r = 0; r < 8; ++r) {
                const int v = r * 32 + lane;
                k8[r] = (v < C) ? lst[v] : 0xffffffffffffffffull;
            }
            bitonic_sort<8>(k8, lane);
            g_nbr[sidx * KNN + lane] = (int)(unsigned)(k8[0] & 0xffffffffull);
        }
    }
}

// ---------------------------------------------------------------------------
// Kernel 3: MLP + max-pool via mma.sync fp16 (single product).
// A = h1 fp16, B = W2 fp16. One mma per tile. h1 in smem, 136-elem row
// stride (conflict-free ldmatrix); B-fragments resident in 64 regs.
// ---------------------------------------------------------------------------
#define ROWSTRIDE 136                       // fp16 elements per h1 row
#define H1_BYTES  (4 * 32 * ROWSTRIDE * 2)  // 34816
#define SM_DYN    H1_BYTES

__global__ void __launch_bounds__(256, 2) k_mlp(const float* __restrict__ pos,
                                                const float* __restrict__ W1,
                                                const float* __restrict__ b1,
                                                const float* __restrict__ b2,
                                                float* __restrict__ out,
                                                int write_extras) {
    extern __shared__ __align__(16) char dyn[];
    __half* h1s = (__half*)dyn;

    __shared__ float w1r[3][H1DIM];
    __shared__ float b1s[H1DIM];
    __shared__ float b2s[H2DIM];
    __shared__ float npx[128], npy[128], npz[128];   // [sample*32 + k]
    __shared__ int   gix[128];
    __shared__ float psmp[4][3];

    const int tid  = threadIdx.x;
    const int lane = tid & 31;
    const int wid  = tid >> 5;
    const int blk  = blockIdx.x;          // NSAMP/4 = 2048

    // ---- B-fragments: 64 u32 per thread, coalesced LDG ----
    uint32_t bfr[8][4][2];
    {
        const uint32_t* fb = g_w2frag + wid * 2048 + lane;
#pragma unroll
        for (int u = 0; u < 64; ++u) {
            const int kt = u >> 3, t = (u >> 1) & 3, h = u & 1;
            bfr[kt][t][h] = fb[u * 32];
        }
    }

    if (tid < H1DIM) {
        w1r[0][tid] = W1[64 * H1DIM + tid];
        w1r[1][tid] = W1[65 * H1DIM + tid];
        w1r[2][tid] = W1[66 * H1DIM + tid];
        b1s[tid]    = b1[tid];
    }
    b2s[tid] = b2[tid];

    // Neighbor metadata for all 4 samples
    if (tid < 128) {
        const int si = tid >> 5;
        const int s  = blk * 4 + si;
        const int b  = s >> 10;
        const int nl = g_nbr[s * KNN + (tid & 31)];
        const int g  = b * NP + nl;
        gix[tid] = g;
        npx[tid] = pos[3 * g];
        npy[tid] = pos[3 * g + 1];
        npz[tid] = pos[3 * g + 2];
    }
    if (tid < 16) {                        // covers psmp[0..3]
        const int si = tid >> 2, c = tid & 3;
        if (c < 3) {
            const int s = blk * 4 + si;
            const int b = s >> 10;
            const int p = b * NP + (s & (NS - 1)) * STRIDE;
            psmp[si][c] = pos[3 * p + c];
        }
    }
    __syncthreads();

    // ---- h1 production: fp32 -> fp16 into padded smem rows ----
    const int j    = tid & 127;           // hidden channel
    const int half = tid >> 7;            // neighbor parity
#pragma unroll
    for (int si = 0; si < 4; ++si) {
        const float psx = psmp[si][0], psy = psmp[si][1], psz = psmp[si][2];
#pragma unroll
        for (int kk = 0; kk < 16; ++kk) {
            const int k = kk * 2 + half;
            const int g = gix[si * 32 + k];
            float rx = npx[si * 32 + k] - psx;
            float ry = npy[si * 32 + k] - psy;
            float rz = npz[si * 32 + k] - psz;
            float v = g_xw1[g * H1DIM + j];
            v = fmaf(rx, w1r[0][j], v);
            v = fmaf(ry, w1r[1][j], v);
            v = fmaf(rz, w1r[2][j], v);
            v += b1s[j];
            v = fmaxf(v, 0.f);
            h1s[(si * 32 + k) * ROWSTRIDE + j] = __float2half_rn(v);
        }
    }
    __syncthreads();

    // ---- per-sample GEMM + max-pool (no further syncs; h1 read-only) ----
    const uint32_t h1_u = smem_u32(h1s);
    const int lrow = lane & 15;
    const int lcol = (lane >> 4) & 1;

    for (int s4 = 0; s4 < 4; ++s4) {
        float acc[2][4][4];
#pragma unroll
        for (int mt = 0; mt < 2; ++mt)
#pragma unroll
            for (int nt = 0; nt < 4; ++nt)
#pragma unroll
                for (int e = 0; e < 4; ++e) acc[mt][nt][e] = 0.f;

#pragma unroll
        for (int kt = 0; kt < 8; ++kt) {
            uint32_t afr[2][4];
#pragma unroll
            for (int mt = 0; mt < 2; ++mt) {
                const uint32_t byteoff =
                    (uint32_t)(((s4 * 32 + mt * 16 + lrow) * ROWSTRIDE +
                                kt * 16 + lcol * 8) * 2);
                ldm_x4(afr[mt], h1_u + byteoff);
            }
#pragma unroll
            for (int mt = 0; mt < 2; ++mt)
#pragma unroll
                for (int nt = 0; nt < 4; ++nt)
                    mma_f16(acc[mt][nt], afr[mt], bfr[kt][nt]);
        }

        // Epilogue: max over 32 neighbor rows, then bias + relu, store.
        const int s = blk * 4 + s4;
#pragma unroll
        for (int nt = 0; nt < 4; ++nt)
#pragma unroll
            for (int par = 0; par < 2; ++par) {
                float m = fmaxf(fmaxf(acc[0][nt][par], acc[0][nt][par + 2]),
                                fmaxf(acc[1][nt][par], acc[1][nt][par + 2]));
                m = fmaxf(m, __shfl_xor_sync(0xffffffffu, m, 4));
                m = fmaxf(m, __shfl_xor_sync(0xffffffffu, m, 8));
                m = fmaxf(m, __shfl_xor_sync(0xffffffffu, m, 16));
                if (lane < 4) {
                    const int c = wid * 32 + nt * 8 + (lane & 3) * 2 + par;
                    out[XOUT_OFF + s * H2DIM + c] = fmaxf(m + b2s[c], 0.f);
                }
            }
    }

    if (write_extras) {
#pragma unroll
        for (int si = 0; si < 4; ++si) {
            const int s = blk * 4 + si;
            const int b = s >> 10;
            const int p = b * NP + (s & (NS - 1)) * STRIDE;
            if (tid < 3)  out[POS_OFF + s * 3 + tid] = psmp[si][tid];
            if (tid == 3) out[BATCH_OFF + s] = (float)b;
            if (tid == 4) out[IDX_OFF + s]   = (float)p;
        }
    }
}

// ---------------------------------------------------------------------------
extern "C" void kernel_launch(void* const* d_in, const int* in_sizes, int n_in,
                              void* d_out, int out_size) {
    const float* x   = (const float*)d_in[0];
    const float* pos = (const float*)d_in[1];
    const float* W1  = (const float*)d_in[3];
    const float* b1  = (const float*)d_in[4];
    const float* W2  = (const float*)d_in[5];
    const float* b2  = (const float*)d_in[6];
    float* out = (float*)d_out;

    const int write_extras = (out_size >= TOTAL_OUT) ? 1 : 0;

    k_xw1<<<NPTS / 8, 128>>>(x, W1);
    k_w2frag<<<64, 256>>>(W2);

    const int smem2 = 3 * NP * (int)sizeof(float)
                    + SPB2 * CAP * (int)sizeof(unsigned long long)
                    + SPB2 * 8 * (int)sizeof(unsigned long long)
                    + SPB2 * (int)sizeof(int);
    cudaFuncSetAttribute(k_knn, cudaFuncAttributeMaxDynamicSharedMemorySize, smem2);
    k_knn<<<BATCHES * (NS / SPB2), 256, smem2>>>(pos);

    cudaFuncSetAttribute(k_mlp, cudaFuncAttributeMaxDynamicSharedMemorySize, SM_DYN);
    k_mlp<<<NSAMP / 4, 256, SM_DYN>>>(pos, W1, b1, b2, out, write_extras);
}

// round 13
// speedup vs baseline: 6.2888x; 1.0248x over previous
#include <cuda_runtime.h>
#include <cuda_fp16.h>
#include <cstdint>

// Problem constants (from reference)
#define BATCHES 8
#define NP 4096
#define STRIDE 4
#define KNN 32
#define NS (NP / STRIDE)          // 1024 samples per batch
#define NSAMP (BATCHES * NS)      // 8192
#define NPTS (BATCHES * NP)       // 32768
#define DIN 64
#define H1DIM 128
#define H2DIM 256

// Output layout (float32 concat of the reference tuple)
#define XOUT_OFF   0
#define POS_OFF    (NSAMP * H2DIM)                 // 2097152
#define BATCH_OFF  (POS_OFF + NSAMP * 3)           // 2121728
#define IDX_OFF    (BATCH_OFF + NSAMP)             // 2129920
#define TOTAL_OUT  (IDX_OFF + NSAMP)               // 2138112

// Scratch (static __device__ arrays: no allocation)
__device__ float g_xw1[NPTS * H1DIM];     // 16 MB: x @ W1[:64]
__device__ int   g_nbr[NSAMP * KNN];      // 1 MB : local neighbor indices
// W2 packed as per-lane mma.sync B-fragments, fp16:
// flat index = wid*2048 + kt*256 + t*64 + h*32 + lane
__device__ uint32_t g_w2frag[16384];      // 64 KB

__device__ __forceinline__ unsigned long long umin64(unsigned long long a,
                                                     unsigned long long b) {
    return b < a ? b : a;
}
__device__ __forceinline__ unsigned long long umax64(unsigned long long a,
                                                     unsigned long long b) {
    return a < b ? b : a;
}

static __device__ __forceinline__ uint32_t smem_u32(const void* p) {
    uint32_t a;
    asm("{ .reg .u64 t; cvta.to.shared.u64 t, %1; cvt.u32.u64 %0, t; }"
        : "=r"(a) : "l"(p));
    return a;
}

// mma.sync fp16 (sm_80+, valid at .target sm_100)
__device__ __forceinline__ void mma_f16(float* d, const uint32_t* a,
                                        const uint32_t* b) {
    asm volatile(
        "mma.sync.aligned.m16n8k16.row.col.f32.f16.f16.f32 "
        "{%0,%1,%2,%3}, {%4,%5,%6,%7}, {%8,%9}, {%0,%1,%2,%3};"
        : "+f"(d[0]), "+f"(d[1]), "+f"(d[2]), "+f"(d[3])
        : "r"(a[0]), "r"(a[1]), "r"(a[2]), "r"(a[3]), "r"(b[0]), "r"(b[1]));
}
__device__ __forceinline__ void ldm_x4(uint32_t* r, uint32_t addr) {
    asm volatile(
        "ldmatrix.sync.aligned.m8n8.x4.shared.b16 {%0,%1,%2,%3}, [%4];"
        : "=r"(r[0]), "=r"(r[1]), "=r"(r[2]), "=r"(r[3]) : "r"(addr));
}

// ---------------------------------------------------------------------------
// Warp-cooperative bitonic sort of N = R*32 u64 keys (R regs/lane).
// ---------------------------------------------------------------------------
template <int R>
__device__ __forceinline__ void bitonic_sort(unsigned long long k[R], int lane) {
    const int N = R * 32;
#pragma unroll
    for (int kk = 2; kk <= N; kk <<= 1) {
#pragma unroll
        for (int j = kk >> 1; j > 0; j >>= 1) {
            if (j >= 32) {
                const int rj = j >> 5;
#pragma unroll
                for (int r = 0; r < R; ++r) {
                    if ((r & rj) == 0) {
                        const int r2 = r | rj;
                        const bool asc = (((r * 32) & kk) == 0);
                        const unsigned long long lo = umin64(k[r], k[r2]);
                        const unsigned long long hi = umax64(k[r], k[r2]);
                        k[r]  = asc ? lo : hi;
                        k[r2] = asc ? hi : lo;
                    }
                }
            } else {
#pragma unroll
                for (int r = 0; r < R; ++r) {
                    const unsigned long long other =
                        __shfl_xor_sync(0xffffffffu, k[r], j);
                    const int v = r * 32 + lane;
                    const bool asc     = ((v & kk) == 0);
                    const bool upper   = ((lane & j) != 0);
                    const bool keepMin = (asc != upper);
                    const unsigned long long mn = umin64(k[r], other);
                    const unsigned long long mx = umax64(k[r], other);
                    k[r] = keepMin ? mn : mx;
                }
            }
        }
    }
}

// ---------------------------------------------------------------------------
// Kernel 1: xw1[n][j] = sum_f x[n][f] * W1[f][j]   (f < 64)   [unchanged]
// ---------------------------------------------------------------------------
__global__ void __launch_bounds__(128) k_xw1(const float* __restrict__ x,
                                             const float* __restrict__ W1) {
    __shared__ float xs[8 * DIN];
    const int p0 = blockIdx.x * 8;
    const int tid = threadIdx.x;
    for (int i = tid; i < 8 * DIN; i += 128) xs[i] = x[p0 * DIN + i];
    __syncthreads();

    float acc[8];
#pragma unroll
    for (int p = 0; p < 8; ++p) acc[p] = 0.f;
#pragma unroll
    for (int f = 0; f < DIN; ++f) {
        float w = W1[f * H1DIM + tid];
#pragma unroll
        for (int p = 0; p < 8; ++p) acc[p] = fmaf(xs[p * DIN + f], w, acc[p]);
    }
#pragma unroll
    for (int p = 0; p < 8; ++p) g_xw1[(p0 + p) * H1DIM + tid] = acc[p];
}

// ---------------------------------------------------------------------------
// Kernel 1b: pack W2 into per-lane mma.sync B-fragments (fp16).  [unchanged]
// ---------------------------------------------------------------------------
__global__ void __launch_bounds__(256) k_w2frag(const float* __restrict__ W2) {
    const int idx  = blockIdx.x * 256 + threadIdx.x;   // 0..16383
    const int lane = idx & 31;
    const int h    = (idx >> 5) & 1;
    const int t    = (idx >> 6) & 3;
    const int kt   = (idx >> 8) & 7;
    const int w    = (idx >> 11) & 7;

    const int k = kt * 16 + (lane & 3) * 2 + 8 * h;
    const int n = w * 32 + t * 8 + (lane >> 2);

    const __half p0 = __float2half_rn(W2[k * H2DIM + n]);
    const __half p1 = __float2half_rn(W2[(k + 1) * H2DIM + n]);
    unsigned short u0, u1;
    memcpy(&u0, &p0, 2);
    memcpy(&u1, &p1, 2);
    g_w2frag[idx] = (uint32_t)u0 | ((uint32_t)u1 << 16);
}

// ---------------------------------------------------------------------------
// Kernel 2: KNN v3 (proven R5 version, unchanged).
// ---------------------------------------------------------------------------
#define SPB2 16
#define CAP  256

__global__ void __launch_bounds__(256) k_knn(const float* __restrict__ pos) {
    extern __shared__ float sm[];
    float* px = sm;
    float* py = sm + NP;
    float* pz = sm + 2 * NP;
    unsigned long long* lists = (unsigned long long*)(sm + 3 * NP); // [16][CAP]
    unsigned long long* warpT = lists + SPB2 * CAP;                 // [16][8]
    int* s_cnt = (int*)(warpT + SPB2 * 8);                          // [16]

    const int tid  = threadIdx.x;
    const int lane = tid & 31;
    const int wid  = tid >> 5;
    const int blk  = blockIdx.x;
    const int b    = blk / (NS / SPB2);
    const int grp  = blk % (NS / SPB2);

    for (int i = tid; i < NP; i += 256) {
        px[i] = pos[(b * NP + i) * 3 + 0];
        py[i] = pos[(b * NP + i) * 3 + 1];
        pz[i] = pos[(b * NP + i) * 3 + 2];
    }
    if (tid < SPB2) s_cnt[tid] = 0;
    __syncthreads();

    for (int si = 0; si < SPB2; ++si) {
        const int s_local = grp * SPB2 + si;
        const int c_local = s_local * STRIDE;
        const float ax = px[c_local], ay = py[c_local], az = pz[c_local];
        const float as2 = __fadd_rn(__fadd_rn(__fmul_rn(ax, ax), __fmul_rn(ay, ay)),
                                    __fmul_rn(az, az));

        unsigned long long keys[16];
#pragma unroll
        for (int t = 0; t < 16; ++t) {
            const int i = tid + t * 256;
            const float bx = px[i], by = py[i], bz = pz[i];
            const float bn2 = __fadd_rn(__fadd_rn(__fmul_rn(bx, bx), __fmul_rn(by, by)),
                                        __fmul_rn(bz, bz));
            const float dot = __fadd_rn(__fadd_rn(__fmul_rn(ax, bx), __fmul_rn(ay, by)),
                                        __fmul_rn(az, bz));
            const float d2  = __fadd_rn(__fadd_rn(as2, bn2), -__fmul_rn(2.0f, dot));
            unsigned u = __float_as_uint(d2);
            unsigned kk = (u & 0x80000000u) ? ~u : (u | 0x80000000u);
            keys[t] = (((unsigned long long)kk) << 32) | (unsigned)i;
        }
        unsigned long long lmin = keys[0];
#pragma unroll
        for (int t = 1; t < 16; ++t) lmin = umin64(lmin, keys[t]);

        unsigned long long tm[1] = { lmin };
        bitonic_sort<1>(tm, lane);
        const unsigned long long Tw = __shfl_sync(0xffffffffu, tm[0], 3);
        if (lane == 0) warpT[si * 8 + wid] = Tw;
        __syncthreads();

        unsigned long long T = warpT[si * 8 + 0];
#pragma unroll
        for (int q = 1; q < 8; ++q) T = umax64(T, warpT[si * 8 + q]);

        int cnt = 0;
#pragma unroll
        for (int t = 0; t < 16; ++t) cnt += (keys[t] <= T) ? 1 : 0;
        int base = atomicAdd(&s_cnt[si], cnt);
        unsigned long long* lst = lists + si * CAP;
#pragma unroll
        for (int t = 0; t < 16; ++t) {
            if (keys[t] <= T) {
                if (base < CAP) lst[base] = keys[t];
                ++base;
            }
        }
    }
    __syncthreads();

    for (int q = 0; q < 2; ++q) {
        const int si = wid + q * 8;
        int C = s_cnt[si];
        if (C > CAP) C = CAP;
        const int s_local = grp * SPB2 + si;
        const int sidx = b * NS + s_local;
        const unsigned long long* lst = lists + si * CAP;

        if (C <= 64) {
            unsigned long long k2[2];
#pragma unroll
            for (int r = 0; r < 2; ++r) {
                const int v = r * 32 + lane;
                k2[r] = (v < C) ? lst[v] : 0xffffffffffffffffull;
            }
            bitonic_sort<2>(k2, lane);
            g_nbr[sidx * KNN + lane] = (int)(unsigned)(k2[0] & 0xffffffffull);
        } else if (C <= 128) {
            unsigned long long k4[4];
#pragma unroll
            for (int r = 0; r < 4; ++r) {
                const int v = r * 32 + lane;
                k4[r] = (v < C) ? lst[v] : 0xffffffffffffffffull;
            }
            bitonic_sort<4>(k4, lane);
            g_nbr[sidx * KNN + lane] = (int)(unsigned)(k4[0] & 0xffffffffull);
        } else {
            unsigned long long k8[8];
#pragma unroll
            for (int r = 0; r < 8; ++r) {
                const int v = r * 32 + lane;
                k8[r] = (v < C) ? lst[v] : 0xffffffffffffffffull;
            }
            bitonic_sort<8>(k8, lane);
            g_nbr[sidx * KNN + lane] = (int)(unsigned)(k8[0] & 0xffffffffull);
        }
    }
}

// ---------------------------------------------------------------------------
// Kernel 3: MLP + max-pool via mma.sync fp16, PERSISTENT CTAs.
// grid = 296 (2/SM); each block loops over sample-groups of 4.
// B-fragments loaded ONCE per block; metadata (npx/gix/psmp) ping-ponged so
// group g+1's LDGs overlap the tail of group g's GEMM. h1 single-buffered
// (the metadata->produce barrier orders GEMM(g-1) readers before writers).
// ---------------------------------------------------------------------------
#define SPB3 4
#define NGRP (NSAMP / SPB3)                 // 2048
#define ROWSTRIDE 136                       // fp16 elements per h1 row
#define H1_BYTES  (SPB3 * 32 * ROWSTRIDE * 2)  // 34816
#define SM_DYN    H1_BYTES
#define MLP_GRID  296

__global__ void __launch_bounds__(256, 2) k_mlp(const float* __restrict__ pos,
                                                const float* __restrict__ W1,
                                                const float* __restrict__ b1,
                                                const float* __restrict__ b2,
                                                float* __restrict__ out,
                                                int write_extras) {
    extern __shared__ __align__(16) char dyn[];
    __half* h1s = (__half*)dyn;

    __shared__ float w1r[3][H1DIM];
    __shared__ float b1s[H1DIM];
    __shared__ float b2s[H2DIM];
    __shared__ float npx[2][128], npy[2][128], npz[2][128];
    __shared__ int   gix[2][128];
    __shared__ float psmp[2][4][3];

    const int tid  = threadIdx.x;
    const int lane = tid & 31;
    const int wid  = tid >> 5;

    // ---- B-fragments: 64 u32 per thread, loaded once per block ----
    uint32_t bfr[8][4][2];
    {
        const uint32_t* fb = g_w2frag + wid * 2048 + lane;
#pragma unroll
        for (int u = 0; u < 64; ++u) {
            const int kt = u >> 3, t = (u >> 1) & 3, h = u & 1;
            bfr[kt][t][h] = fb[u * 32];
        }
    }

    if (tid < H1DIM) {
        w1r[0][tid] = W1[64 * H1DIM + tid];
        w1r[1][tid] = W1[65 * H1DIM + tid];
        w1r[2][tid] = W1[66 * H1DIM + tid];
        b1s[tid]    = b1[tid];
    }
    b2s[tid] = b2[tid];

    const uint32_t h1_u = smem_u32(h1s);
    const int j    = tid & 127;           // hidden channel
    const int half = tid >> 7;            // neighbor parity
    const int lrow = lane & 15;
    const int lcol = (lane >> 4) & 1;

    for (int g = blockIdx.x; g < NGRP; g += gridDim.x) {
        const int buf = g & 1;

        // ---- metadata for this group (overlaps prior group's GEMM) ----
        if (tid < 128) {
            const int si = tid >> 5;
            const int s  = g * 4 + si;
            const int b  = s >> 10;
            const int nl = g_nbr[s * KNN + (tid & 31)];
            const int gg = b * NP + nl;
            gix[buf][tid] = gg;
            npx[buf][tid] = pos[3 * gg];
            npy[buf][tid] = pos[3 * gg + 1];
            npz[buf][tid] = pos[3 * gg + 2];
        }
        if (tid < 16) {                    // covers psmp[buf][0..3]
            const int si = tid >> 2, c = tid & 3;
            if (c < 3) {
                const int s = g * 4 + si;
                const int b = s >> 10;
                const int p = b * NP + (s & (NS - 1)) * STRIDE;
                psmp[buf][si][c] = pos[3 * p + c];
            }
        }
        __syncthreads();   // S1: meta visible; also GEMM(g-1) done -> h1 free

        // ---- h1 production: fp32 -> fp16 into padded smem rows ----
#pragma unroll
        for (int si = 0; si < 4; ++si) {
            const float psx = psmp[buf][si][0];
            const float psy = psmp[buf][si][1];
            const float psz = psmp[buf][si][2];
#pragma unroll
            for (int kk = 0; kk < 16; ++kk) {
                const int k = kk * 2 + half;
                const int gg = gix[buf][si * 32 + k];
                float rx = npx[buf][si * 32 + k] - psx;
                float ry = npy[buf][si * 32 + k] - psy;
                float rz = npz[buf][si * 32 + k] - psz;
                float v = g_xw1[gg * H1DIM + j];
                v = fmaf(rx, w1r[0][j], v);
                v = fmaf(ry, w1r[1][j], v);
                v = fmaf(rz, w1r[2][j], v);
                v += b1s[j];
                v = fmaxf(v, 0.f);
                h1s[(si * 32 + k) * ROWSTRIDE + j] = __float2half_rn(v);
            }
        }
        __syncthreads();   // S2: h1 ready

        // ---- per-sample GEMM + max-pool ----
        for (int s4 = 0; s4 < 4; ++s4) {
            float acc[2][4][4];
#pragma unroll
            for (int mt = 0; mt < 2; ++mt)
#pragma unroll
                for (int nt = 0; nt < 4; ++nt)
#pragma unroll
                    for (int e = 0; e < 4; ++e) acc[mt][nt][e] = 0.f;

#pragma unroll
            for (int kt = 0; kt < 8; ++kt) {
                uint32_t afr[2][4];
#pragma unroll
                for (int mt = 0; mt < 2; ++mt) {
                    const uint32_t byteoff =
                        (uint32_t)(((s4 * 32 + mt * 16 + lrow) * ROWSTRIDE +
                                    kt * 16 + lcol * 8) * 2);
                    ldm_x4(afr[mt], h1_u + byteoff);
                }
#pragma unroll
                for (int mt = 0; mt < 2; ++mt)
#pragma unroll
                    for (int nt = 0; nt < 4; ++nt)
                        mma_f16(acc[mt][nt], afr[mt], bfr[kt][nt]);
            }

            const int s = g * 4 + s4;
#pragma unroll
            for (int nt = 0; nt < 4; ++nt)
#pragma unroll
                for (int par = 0; par < 2; ++par) {
                    float m = fmaxf(fmaxf(acc[0][nt][par], acc[0][nt][par + 2]),
                                    fmaxf(acc[1][nt][par], acc[1][nt][par + 2]));
                    m = fmaxf(m, __shfl_xor_sync(0xffffffffu, m, 4));
                    m = fmaxf(m, __shfl_xor_sync(0xffffffffu, m, 8));
                    m = fmaxf(m, __shfl_xor_sync(0xffffffffu, m, 16));
                    if (lane < 4) {
                        const int c = wid * 32 + nt * 8 + (lane & 3) * 2 + par;
                        out[XOUT_OFF + s * H2DIM + c] = fmaxf(m + b2s[c], 0.f);
                    }
                }
        }

        if (write_extras) {
#pragma unroll
            for (int si = 0; si < 4; ++si) {
                const int s = g * 4 + si;
                const int b = s >> 10;
                const int p = b * NP + (s & (NS - 1)) * STRIDE;
                if (tid < 3)  out[POS_OFF + s * 3 + tid] = psmp[buf][si][tid];
                if (tid == 3) out[BATCH_OFF + s] = (float)b;
                if (tid == 4) out[IDX_OFF + s]   = (float)p;
            }
        }
        // no trailing sync: next iteration writes the OTHER metadata buffer,
        // and S1 there orders h1 reuse.
    }
}

// ---------------------------------------------------------------------------
extern "C" void kernel_launch(void* const* d_in, const int* in_sizes, int n_in,
                              void* d_out, int out_size) {
    const float* x   = (const float*)d_in[0];
    const float* pos = (const float*)d_in[1];
    const float* W1  = (const float*)d_in[3];
    const float* b1  = (const float*)d_in[4];
    const float* W2  = (const float*)d_in[5];
    const float* b2  = (const float*)d_in[6];
    float* out = (float*)d_out;

    const int write_extras = (out_size >= TOTAL_OUT) ? 1 : 0;

    k_xw1<<<NPTS / 8, 128>>>(x, W1);
    k_w2frag<<<64, 256>>>(W2);

    const int smem2 = 3 * NP * (int)sizeof(float)
                    + SPB2 * CAP * (int)sizeof(unsigned long long)
                    + SPB2 * 8 * (int)sizeof(unsigned long long)
                    + SPB2 * (int)sizeof(int);
    cudaFuncSetAttribute(k_knn, cudaFuncAttributeMaxDynamicSharedMemorySize, smem2);
    k_knn<<<BATCHES * (NS / SPB2), 256, smem2>>>(pos);

    cudaFuncSetAttribute(k_mlp, cudaFuncAttributeMaxDynamicSharedMemorySize, SM_DYN);
    k_mlp<<<MLP_GRID, 256, SM_DYN>>>(pos, W1, b1, b2, out, write_extras);
}

// round 14
// speedup vs baseline: 6.3854x; 1.0154x over previous
#include <cuda_runtime.h>
#include <cuda_fp16.h>
#include <cstdint>

// Problem constants (from reference)
#define BATCHES 8
#define NP 4096
#define STRIDE 4
#define KNN 32
#define NS (NP / STRIDE)          // 1024 samples per batch
#define NSAMP (BATCHES * NS)      // 8192
#define NPTS (BATCHES * NP)       // 32768
#define DIN 64
#define H1DIM 128
#define H2DIM 256

// Output layout (float32 concat of the reference tuple)
#define XOUT_OFF   0
#define POS_OFF    (NSAMP * H2DIM)                 // 2097152
#define BATCH_OFF  (POS_OFF + NSAMP * 3)           // 2121728
#define IDX_OFF    (BATCH_OFF + NSAMP)             // 2129920
#define TOTAL_OUT  (IDX_OFF + NSAMP)               // 2138112

// Scratch (static __device__ arrays: no allocation)
__device__ float g_xw1[NPTS * H1DIM];     // 16 MB: x @ W1[:64]
__device__ int   g_nbr[NSAMP * KNN];      // 1 MB : local neighbor indices
// W2 packed as per-lane mma.sync B-fragments, fp16:
// flat index = wid*2048 + kt*256 + t*64 + h*32 + lane
__device__ uint32_t g_w2frag[16384];      // 64 KB

__device__ __forceinline__ unsigned long long umin64(unsigned long long a,
                                                     unsigned long long b) {
    return b < a ? b : a;
}
__device__ __forceinline__ unsigned long long umax64(unsigned long long a,
                                                     unsigned long long b) {
    return a < b ? b : a;
}

static __device__ __forceinline__ uint32_t smem_u32(const void* p) {
    uint32_t a;
    asm("{ .reg .u64 t; cvta.to.shared.u64 t, %1; cvt.u32.u64 %0, t; }"
        : "=r"(a) : "l"(p));
    return a;
}

// mma.sync fp16 (sm_80+, valid at .target sm_100)
__device__ __forceinline__ void mma_f16(float* d, const uint32_t* a,
                                        const uint32_t* b) {
    asm volatile(
        "mma.sync.aligned.m16n8k16.row.col.f32.f16.f16.f32 "
        "{%0,%1,%2,%3}, {%4,%5,%6,%7}, {%8,%9}, {%0,%1,%2,%3};"
        : "+f"(d[0]), "+f"(d[1]), "+f"(d[2]), "+f"(d[3])
        : "r"(a[0]), "r"(a[1]), "r"(a[2]), "r"(a[3]), "r"(b[0]), "r"(b[1]));
}
__device__ __forceinline__ void ldm_x4(uint32_t* r, uint32_t addr) {
    asm volatile(
        "ldmatrix.sync.aligned.m8n8.x4.shared.b16 {%0,%1,%2,%3}, [%4];"
        : "=r"(r[0]), "=r"(r[1]), "=r"(r[2]), "=r"(r[3]) : "r"(addr));
}

// ---------------------------------------------------------------------------
// Warp-cooperative bitonic sort of N = R*32 u64 keys (R regs/lane).
// ---------------------------------------------------------------------------
template <int R>
__device__ __forceinline__ void bitonic_sort(unsigned long long k[R], int lane) {
    const int N = R * 32;
#pragma unroll
    for (int kk = 2; kk <= N; kk <<= 1) {
#pragma unroll
        for (int j = kk >> 1; j > 0; j >>= 1) {
            if (j >= 32) {
                const int rj = j >> 5;
#pragma unroll
                for (int r = 0; r < R; ++r) {
                    if ((r & rj) == 0) {
                        const int r2 = r | rj;
                        const bool asc = (((r * 32) & kk) == 0);
                        const unsigned long long lo = umin64(k[r], k[r2]);
                        const unsigned long long hi = umax64(k[r], k[r2]);
                        k[r]  = asc ? lo : hi;
                        k[r2] = asc ? hi : lo;
                    }
                }
            } else {
#pragma unroll
                for (int r = 0; r < R; ++r) {
                    const unsigned long long other =
                        __shfl_xor_sync(0xffffffffu, k[r], j);
                    const int v = r * 32 + lane;
                    const bool asc     = ((v & kk) == 0);
                    const bool upper   = ((lane & j) != 0);
                    const bool keepMin = (asc != upper);
                    const unsigned long long mn = umin64(k[r], other);
                    const unsigned long long mx = umax64(k[r], other);
                    k[r] = keepMin ? mn : mx;
                }
            }
        }
    }
}

// ---------------------------------------------------------------------------
// MERGED prep kernel: blocks [0,512) = KNN, [512,2560) = xw1, [2560,2624) =
// w2frag. All three are independent; running them in one launch lets xw1's
// FMA work fill the idle issue slots of the latency-bound KNN blocks.
// ---------------------------------------------------------------------------
#define SPB2 16
#define CAP  256
#define KNN_BLOCKS  (BATCHES * (NS / SPB2))          // 512
#define XW1_BLOCKS  (NPTS / 16)                      // 2048
#define W2F_BLOCKS  64
#define PRE_GRID    (KNN_BLOCKS + XW1_BLOCKS + W2F_BLOCKS)
#define PRE_SMEM    (3 * NP * 4 + SPB2 * CAP * 8 + SPB2 * 8 * 8 + SPB2 * 4)

__device__ void knn_body(const float* __restrict__ pos, char* smraw, int blk) {
    float* sm = (float*)smraw;
    float* px = sm;
    float* py = sm + NP;
    float* pz = sm + 2 * NP;
    unsigned long long* lists = (unsigned long long*)(sm + 3 * NP); // [16][CAP]
    unsigned long long* warpT = lists + SPB2 * CAP;                 // [16][8]
    int* s_cnt = (int*)(warpT + SPB2 * 8);                          // [16]

    const int tid  = threadIdx.x;
    const int lane = tid & 31;
    const int wid  = tid >> 5;
    const int b    = blk / (NS / SPB2);
    const int grp  = blk % (NS / SPB2);

    for (int i = tid; i < NP; i += 256) {
        px[i] = pos[(b * NP + i) * 3 + 0];
        py[i] = pos[(b * NP + i) * 3 + 1];
        pz[i] = pos[(b * NP + i) * 3 + 2];
    }
    if (tid < SPB2) s_cnt[tid] = 0;
    __syncthreads();

    for (int si = 0; si < SPB2; ++si) {
        const int s_local = grp * SPB2 + si;
        const int c_local = s_local * STRIDE;
        const float ax = px[c_local], ay = py[c_local], az = pz[c_local];
        const float as2 = __fadd_rn(__fadd_rn(__fmul_rn(ax, ax), __fmul_rn(ay, ay)),
                                    __fmul_rn(az, az));

        unsigned long long keys[16];
#pragma unroll
        for (int t = 0; t < 16; ++t) {
            const int i = tid + t * 256;
            const float bx = px[i], by = py[i], bz = pz[i];
            const float bn2 = __fadd_rn(__fadd_rn(__fmul_rn(bx, bx), __fmul_rn(by, by)),
                                        __fmul_rn(bz, bz));
            const float dot = __fadd_rn(__fadd_rn(__fmul_rn(ax, bx), __fmul_rn(ay, by)),
                                        __fmul_rn(az, bz));
            const float d2  = __fadd_rn(__fadd_rn(as2, bn2), -__fmul_rn(2.0f, dot));
            unsigned u = __float_as_uint(d2);
            unsigned kk = (u & 0x80000000u) ? ~u : (u | 0x80000000u);
            keys[t] = (((unsigned long long)kk) << 32) | (unsigned)i;
        }
        unsigned long long lmin = keys[0];
#pragma unroll
        for (int t = 1; t < 16; ++t) lmin = umin64(lmin, keys[t]);

        unsigned long long tm[1] = { lmin };
        bitonic_sort<1>(tm, lane);
        const unsigned long long Tw = __shfl_sync(0xffffffffu, tm[0], 3);
        if (lane == 0) warpT[si * 8 + wid] = Tw;
        __syncthreads();

        unsigned long long T = warpT[si * 8 + 0];
#pragma unroll
        for (int q = 1; q < 8; ++q) T = umax64(T, warpT[si * 8 + q]);

        int cnt = 0;
#pragma unroll
        for (int t = 0; t < 16; ++t) cnt += (keys[t] <= T) ? 1 : 0;
        int base = atomicAdd(&s_cnt[si], cnt);
        unsigned long long* lst = lists + si * CAP;
#pragma unroll
        for (int t = 0; t < 16; ++t) {
            if (keys[t] <= T) {
                if (base < CAP) lst[base] = keys[t];
                ++base;
            }
        }
    }
    __syncthreads();

    for (int q = 0; q < 2; ++q) {
        const int si = wid + q * 8;
        int C = s_cnt[si];
        if (C > CAP) C = CAP;
        const int s_local = grp * SPB2 + si;
        const int sidx = b * NS + s_local;
        const unsigned long long* lst = lists + si * CAP;

        if (C <= 64) {
            unsigned long long k2[2];
#pragma unroll
            for (int r = 0; r < 2; ++r) {
                const int v = r * 32 + lane;
                k2[r] = (v < C) ? lst[v] : 0xffffffffffffffffull;
            }
            bitonic_sort<2>(k2, lane);
            g_nbr[sidx * KNN + lane] = (int)(unsigned)(k2[0] & 0xffffffffull);
        } else if (C <= 128) {
            unsigned long long k4[4];
#pragma unroll
            for (int r = 0; r < 4; ++r) {
                const int v = r * 32 + lane;
                k4[r] = (v < C) ? lst[v] : 0xffffffffffffffffull;
            }
            bitonic_sort<4>(k4, lane);
            g_nbr[sidx * KNN + lane] = (int)(unsigned)(k4[0] & 0xffffffffull);
        } else {
            unsigned long long k8[8];
#pragma unroll
            for (int r = 0; r < 8; ++r) {
                const int v = r * 32 + lane;
                k8[r] = (v < C) ? lst[v] : 0xffffffffffffffffull;
            }
            bitonic_sort<8>(k8, lane);
            g_nbr[sidx * KNN + lane] = (int)(unsigned)(k8[0] & 0xffffffffull);
        }
    }
}

__device__ void xw1_body(const float* __restrict__ x,
                         const float* __restrict__ W1, char* smraw, int blk) {
    float* xs = (float*)smraw;            // 16 * 64 floats
    const int p0 = blk * 16;
    const int tid = threadIdx.x;
    for (int i = tid; i < 16 * DIN; i += 256) xs[i] = x[p0 * DIN + i];
    __syncthreads();

    const int j = tid & 127;
    const int h = tid >> 7;               // points 8h..8h+7
    float acc[8];
#pragma unroll
    for (int p = 0; p < 8; ++p) acc[p] = 0.f;
#pragma unroll
    for (int f = 0; f < DIN; ++f) {
        float w = W1[f * H1DIM + j];
#pragma unroll
        for (int p = 0; p < 8; ++p)
            acc[p] = fmaf(xs[(h * 8 + p) * DIN + f], w, acc[p]);
    }
#pragma unroll
    for (int p = 0; p < 8; ++p)
        g_xw1[(p0 + h * 8 + p) * H1DIM + j] = acc[p];
}

__device__ void w2frag_body(const float* __restrict__ W2, int blk) {
    const int idx  = blk * 256 + threadIdx.x;   // 0..16383
    const int lane = idx & 31;
    const int h    = (idx >> 5) & 1;
    const int t    = (idx >> 6) & 3;
    const int kt   = (idx >> 8) & 7;
    const int w    = (idx >> 11) & 7;

    const int k = kt * 16 + (lane & 3) * 2 + 8 * h;
    const int n = w * 32 + t * 8 + (lane >> 2);

    const __half p0 = __float2half_rn(W2[k * H2DIM + n]);
    const __half p1 = __float2half_rn(W2[(k + 1) * H2DIM + n]);
    unsigned short u0, u1;
    memcpy(&u0, &p0, 2);
    memcpy(&u1, &p1, 2);
    g_w2frag[idx] = (uint32_t)u0 | ((uint32_t)u1 << 16);
}

__global__ void __launch_bounds__(256) k_pre(const float* __restrict__ x,
                                             const float* __restrict__ pos,
                                             const float* __restrict__ W1,
                                             const float* __restrict__ W2) {
    extern __shared__ char smraw[];
    const int bid = blockIdx.x;
    if (bid < KNN_BLOCKS) {
        knn_body(pos, smraw, bid);
    } else if (bid < KNN_BLOCKS + XW1_BLOCKS) {
        xw1_body(x, W1, smraw, bid - KNN_BLOCKS);
    } else {
        w2frag_body(W2, bid - KNN_BLOCKS - XW1_BLOCKS);
    }
}

// ---------------------------------------------------------------------------
// Kernel 3: MLP + max-pool, persistent CTAs, ONE barrier per group.
// Produce reads all metadata directly from gmem (broadcast/coalesced LDGs,
// no smem meta, no meta barrier). h1 double-buffered; per iteration:
//   GEMM(g) from buf[i&1]  ||  produce(g+grid) into buf[(i+1)&1]  -> sync
// ---------------------------------------------------------------------------
#define SPB3 4
#define NGRP (NSAMP / SPB3)                 // 2048
#define ROWSTRIDE 136                       // fp16 elements per h1 row
#define H1_BYTES  (SPB3 * 32 * ROWSTRIDE * 2)  // 34816
#define SM_DYN    (2 * H1_BYTES)            // 69632
#define MLP_GRID  296

__global__ void __launch_bounds__(256, 2) k_mlp(const float* __restrict__ pos,
                                                const float* __restrict__ W1,
                                                const float* __restrict__ b1,
                                                const float* __restrict__ b2,
                                                float* __restrict__ out,
                                                int write_extras) {
    extern __shared__ __align__(16) char dyn[];
    __half* h1buf[2] = { (__half*)dyn, (__half*)(dyn + H1_BYTES) };

    __shared__ float w1r[3][H1DIM];
    __shared__ float b1s[H1DIM];
    __shared__ float b2s[H2DIM];

    const int tid  = threadIdx.x;
    const int lane = tid & 31;
    const int wid  = tid >> 5;

    // ---- B-fragments: 64 u32 per thread, loaded once per block ----
    uint32_t bfr[8][4][2];
    {
        const uint32_t* fb = g_w2frag + wid * 2048 + lane;
#pragma unroll
        for (int u = 0; u < 64; ++u) {
            const int kt = u >> 3, t = (u >> 1) & 3, h = u & 1;
            bfr[kt][t][h] = fb[u * 32];
        }
    }

    if (tid < H1DIM) {
        w1r[0][tid] = W1[64 * H1DIM + tid];
        w1r[1][tid] = W1[65 * H1DIM + tid];
        w1r[2][tid] = W1[66 * H1DIM + tid];
        b1s[tid]    = b1[tid];
    }
    b2s[tid] = b2[tid];
    __syncthreads();                       // consts visible

    const int j    = tid & 127;            // hidden channel
    const int half = tid >> 7;             // neighbor parity
    const int lrow = lane & 15;
    const int lcol = (lane >> 4) & 1;

    // produce h1 for group g into buf (all metadata straight from gmem)
    auto produce = [&](int g, __half* buf) {
#pragma unroll
        for (int si = 0; si < SPB3; ++si) {
            const int s = g * SPB3 + si;
            const int b = s >> 10;
            const int p = b * NP + (s & (NS - 1)) * STRIDE;
            const float psx = pos[3 * p];
            const float psy = pos[3 * p + 1];
            const float psz = pos[3 * p + 2];
#pragma unroll
            for (int kk = 0; kk < 16; ++kk) {
                const int k  = kk * 2 + half;
                const int gg = b * NP + g_nbr[s * KNN + k];   // broadcast
                float rx = pos[3 * gg]     - psx;
                float ry = pos[3 * gg + 1] - psy;
                float rz = pos[3 * gg + 2] - psz;
                float v = g_xw1[gg * H1DIM + j];              // coalesced
                v = fmaf(rx, w1r[0][j], v);
                v = fmaf(ry, w1r[1][j], v);
                v = fmaf(rz, w1r[2][j], v);
                v += b1s[j];
                v = fmaxf(v, 0.f);
                buf[(si * 32 + k) * ROWSTRIDE + j] = __float2half_rn(v);
            }
        }
    };

    int g = blockIdx.x;
    int i = 0;
    if (g < NGRP) produce(g, h1buf[0]);
    __syncthreads();

    for (; g < NGRP; g += gridDim.x, ++i) {
        const uint32_t h1_u = smem_u32(h1buf[i & 1]);

        // ---- per-sample GEMM + max-pool on buf[i&1] ----
        for (int s4 = 0; s4 < SPB3; ++s4) {
            float acc[2][4][4];
#pragma unroll
            for (int mt = 0; mt < 2; ++mt)
#pragma unroll
                for (int nt = 0; nt < 4; ++nt)
#pragma unroll
                    for (int e = 0; e < 4; ++e) acc[mt][nt][e] = 0.f;

#pragma unroll
            for (int kt = 0; kt < 8; ++kt) {
                uint32_t afr[2][4];
#pragma unroll
                for (int mt = 0; mt < 2; ++mt) {
                    const uint32_t byteoff =
                        (uint32_t)(((s4 * 32 + mt * 16 + lrow) * ROWSTRIDE +
                                    kt * 16 + lcol * 8) * 2);
                    ldm_x4(afr[mt], h1_u + byteoff);
                }
#pragma unroll
                for (int mt = 0; mt < 2; ++mt)
#pragma unroll
                    for (int nt = 0; nt < 4; ++nt)
                        mma_f16(acc[mt][nt], afr[mt], bfr[kt][nt]);
            }

            const int s = g * SPB3 + s4;
#pragma unroll
            for (int nt = 0; nt < 4; ++nt)
#pragma unroll
                for (int par = 0; par < 2; ++par) {
                    float m = fmaxf(fmaxf(acc[0][nt][par], acc[0][nt][par + 2]),
                                    fmaxf(acc[1][nt][par], acc[1][nt][par + 2]));
                    m = fmaxf(m, __shfl_xor_sync(0xffffffffu, m, 4));
                    m = fmaxf(m, __shfl_xor_sync(0xffffffffu, m, 8));
                    m = fmaxf(m, __shfl_xor_sync(0xffffffffu, m, 16));
                    if (lane < 4) {
                        const int c = wid * 32 + nt * 8 + (lane & 3) * 2 + par;
                        out[XOUT_OFF + s * H2DIM + c] = fmaxf(m + b2s[c], 0.f);
                    }
                }
        }

        if (write_extras) {
#pragma unroll
            for (int si = 0; si < SPB3; ++si) {
                const int s = g * SPB3 + si;
                const int b = s >> 10;
                const int p = b * NP + (s & (NS - 1)) * STRIDE;
                if (tid < 3)  out[POS_OFF + s * 3 + tid] = pos[3 * p + tid];
                if (tid == 3) out[BATCH_OFF + s] = (float)b;
                if (tid == 4) out[IDX_OFF + s]   = (float)p;
            }
        }

        // ---- produce next group into the other buffer (overlaps GEMM) ----
        const int gn = g + gridDim.x;
        if (gn < NGRP) produce(gn, h1buf[(i + 1) & 1]);
        __syncthreads();   // single barrier per group
    }
}

// ---------------------------------------------------------------------------
extern "C" void kernel_launch(void* const* d_in, const int* in_sizes, int n_in,
                              void* d_out, int out_size) {
    const float* x   = (const float*)d_in[0];
    const float* pos = (const float*)d_in[1];
    const float* W1  = (const float*)d_in[3];
    const float* b1  = (const float*)d_in[4];
    const float* W2  = (const float*)d_in[5];
    const float* b2  = (const float*)d_in[6];
    float* out = (float*)d_out;

    const int write_extras = (out_size >= TOTAL_OUT) ? 1 : 0;

    cudaFuncSetAttribute(k_pre, cudaFuncAttributeMaxDynamicSharedMemorySize,
                         PRE_SMEM);
    k_pre<<<PRE_GRID, 256, PRE_SMEM>>>(x, pos, W1, W2);

    cudaFuncSetAttribute(k_mlp, cudaFuncAttributeMaxDynamicSharedMemorySize,
                         SM_DYN);
    k_mlp<<<MLP_GRID, 256, SM_DYN>>>(pos, W1, b1, b2, out, write_extras);
}

// round 15
// speedup vs baseline: 6.6413x; 1.0401x over previous
#include <cuda_runtime.h>
#include <cuda_fp16.h>
#include <cstdint>

// Problem constants (from reference)
#define BATCHES 8
#define NP 4096
#define STRIDE 4
#define KNN 32
#define NS (NP / STRIDE)          // 1024 samples per batch
#define NSAMP (BATCHES * NS)      // 8192
#define NPTS (BATCHES * NP)       // 32768
#define DIN 64
#define H1DIM 128
#define H2DIM 256

// Output layout (float32 concat of the reference tuple)
#define XOUT_OFF   0
#define POS_OFF    (NSAMP * H2DIM)                 // 2097152
#define BATCH_OFF  (POS_OFF + NSAMP * 3)           // 2121728
#define IDX_OFF    (BATCH_OFF + NSAMP)             // 2129920
#define TOTAL_OUT  (IDX_OFF + NSAMP)               // 2138112

// Scratch (static __device__ arrays: no allocation)
__device__ float g_xw1[NPTS * H1DIM];     // 16 MB: x @ W1[:64]
__device__ int   g_nbr[NSAMP * KNN];      // 1 MB : local neighbor indices
// W2 packed as per-lane mma.sync B-fragments, fp16:
// flat index = wid*2048 + kt*256 + t*64 + h*32 + lane
__device__ uint32_t g_w2frag[16384];      // 64 KB

__device__ __forceinline__ unsigned long long umin64(unsigned long long a,
                                                     unsigned long long b) {
    return b < a ? b : a;
}
__device__ __forceinline__ unsigned long long umax64(unsigned long long a,
                                                     unsigned long long b) {
    return a < b ? b : a;
}

static __device__ __forceinline__ uint32_t smem_u32(const void* p) {
    uint32_t a;
    asm("{ .reg .u64 t; cvta.to.shared.u64 t, %1; cvt.u32.u64 %0, t; }"
        : "=r"(a) : "l"(p));
    return a;
}

// mma.sync fp16 (sm_80+, valid at .target sm_100)
__device__ __forceinline__ void mma_f16(float* d, const uint32_t* a,
                                        const uint32_t* b) {
    asm volatile(
        "mma.sync.aligned.m16n8k16.row.col.f32.f16.f16.f32 "
        "{%0,%1,%2,%3}, {%4,%5,%6,%7}, {%8,%9}, {%0,%1,%2,%3};"
        : "+f"(d[0]), "+f"(d[1]), "+f"(d[2]), "+f"(d[3])
        : "r"(a[0]), "r"(a[1]), "r"(a[2]), "r"(a[3]), "r"(b[0]), "r"(b[1]));
}
__device__ __forceinline__ void ldm_x4(uint32_t* r, uint32_t addr) {
    asm volatile(
        "ldmatrix.sync.aligned.m8n8.x4.shared.b16 {%0,%1,%2,%3}, [%4];"
        : "=r"(r[0]), "=r"(r[1]), "=r"(r[2]), "=r"(r[3]) : "r"(addr));
}

// ---------------------------------------------------------------------------
// Warp-cooperative bitonic sort of N = R*32 u64 keys (R regs/lane).
// ---------------------------------------------------------------------------
template <int R>
__device__ __forceinline__ void bitonic_sort(unsigned long long k[R], int lane) {
    const int N = R * 32;
#pragma unroll
    for (int kk = 2; kk <= N; kk <<= 1) {
#pragma unroll
        for (int j = kk >> 1; j > 0; j >>= 1) {
            if (j >= 32) {
                const int rj = j >> 5;
#pragma unroll
                for (int r = 0; r < R; ++r) {
                    if ((r & rj) == 0) {
                        const int r2 = r | rj;
                        const bool asc = (((r * 32) & kk) == 0);
                        const unsigned long long lo = umin64(k[r], k[r2]);
                        const unsigned long long hi = umax64(k[r], k[r2]);
                        k[r]  = asc ? lo : hi;
                        k[r2] = asc ? hi : lo;
                    }
                }
            } else {
#pragma unroll
                for (int r = 0; r < R; ++r) {
                    const unsigned long long other =
                        __shfl_xor_sync(0xffffffffu, k[r], j);
                    const int v = r * 32 + lane;
                    const bool asc     = ((v & kk) == 0);
                    const bool upper   = ((lane & j) != 0);
                    const bool keepMin = (asc != upper);
                    const unsigned long long mn = umin64(k[r], other);
                    const unsigned long long mx = umax64(k[r], other);
                    k[r] = keepMin ? mn : mx;
                }
            }
        }
    }
}

// ---------------------------------------------------------------------------
// MERGED prep kernel (R14, proven): blocks [0,512) = KNN, [512,2560) = xw1,
// [2560,2624) = w2frag. Independent bodies; xw1's FMA work fills the idle
// issue slots of the latency-bound KNN blocks.
// ---------------------------------------------------------------------------
#define SPB2 16
#define CAP  256
#define KNN_BLOCKS  (BATCHES * (NS / SPB2))          // 512
#define XW1_BLOCKS  (NPTS / 16)                      // 2048
#define W2F_BLOCKS  64
#define PRE_GRID    (KNN_BLOCKS + XW1_BLOCKS + W2F_BLOCKS)
#define PRE_SMEM    (3 * NP * 4 + SPB2 * CAP * 8 + SPB2 * 8 * 8 + SPB2 * 4)

__device__ void knn_body(const float* __restrict__ pos, char* smraw, int blk) {
    float* sm = (float*)smraw;
    float* px = sm;
    float* py = sm + NP;
    float* pz = sm + 2 * NP;
    unsigned long long* lists = (unsigned long long*)(sm + 3 * NP); // [16][CAP]
    unsigned long long* warpT = lists + SPB2 * CAP;                 // [16][8]
    int* s_cnt = (int*)(warpT + SPB2 * 8);                          // [16]

    const int tid  = threadIdx.x;
    const int lane = tid & 31;
    const int wid  = tid >> 5;
    const int b    = blk / (NS / SPB2);
    const int grp  = blk % (NS / SPB2);

    for (int i = tid; i < NP; i += 256) {
        px[i] = pos[(b * NP + i) * 3 + 0];
        py[i] = pos[(b * NP + i) * 3 + 1];
        pz[i] = pos[(b * NP + i) * 3 + 2];
    }
    if (tid < SPB2) s_cnt[tid] = 0;
    __syncthreads();

    for (int si = 0; si < SPB2; ++si) {
        const int s_local = grp * SPB2 + si;
        const int c_local = s_local * STRIDE;
        const float ax = px[c_local], ay = py[c_local], az = pz[c_local];
        const float as2 = __fadd_rn(__fadd_rn(__fmul_rn(ax, ax), __fmul_rn(ay, ay)),
                                    __fmul_rn(az, az));

        unsigned long long keys[16];
#pragma unroll
        for (int t = 0; t < 16; ++t) {
            const int i = tid + t * 256;
            const float bx = px[i], by = py[i], bz = pz[i];
            const float bn2 = __fadd_rn(__fadd_rn(__fmul_rn(bx, bx), __fmul_rn(by, by)),
                                        __fmul_rn(bz, bz));
            const float dot = __fadd_rn(__fadd_rn(__fmul_rn(ax, bx), __fmul_rn(ay, by)),
                                        __fmul_rn(az, bz));
            const float d2  = __fadd_rn(__fadd_rn(as2, bn2), -__fmul_rn(2.0f, dot));
            unsigned u = __float_as_uint(d2);
            unsigned kk = (u & 0x80000000u) ? ~u : (u | 0x80000000u);
            keys[t] = (((unsigned long long)kk) << 32) | (unsigned)i;
        }
        unsigned long long lmin = keys[0];
#pragma unroll
        for (int t = 1; t < 16; ++t) lmin = umin64(lmin, keys[t]);

        unsigned long long tm[1] = { lmin };
        bitonic_sort<1>(tm, lane);
        const unsigned long long Tw = __shfl_sync(0xffffffffu, tm[0], 3);
        if (lane == 0) warpT[si * 8 + wid] = Tw;
        __syncthreads();

        unsigned long long T = warpT[si * 8 + 0];
#pragma unroll
        for (int q = 1; q < 8; ++q) T = umax64(T, warpT[si * 8 + q]);

        int cnt = 0;
#pragma unroll
        for (int t = 0; t < 16; ++t) cnt += (keys[t] <= T) ? 1 : 0;
        int base = atomicAdd(&s_cnt[si], cnt);
        unsigned long long* lst = lists + si * CAP;
#pragma unroll
        for (int t = 0; t < 16; ++t) {
            if (keys[t] <= T) {
                if (base < CAP) lst[base] = keys[t];
                ++base;
            }
        }
    }
    __syncthreads();

    for (int q = 0; q < 2; ++q) {
        const int si = wid + q * 8;
        int C = s_cnt[si];
        if (C > CAP) C = CAP;
        const int s_local = grp * SPB2 + si;
        const int sidx = b * NS + s_local;
        const unsigned long long* lst = lists + si * CAP;

        if (C <= 64) {
            unsigned long long k2[2];
#pragma unroll
            for (int r = 0; r < 2; ++r) {
                const int v = r * 32 + lane;
                k2[r] = (v < C) ? lst[v] : 0xffffffffffffffffull;
            }
            bitonic_sort<2>(k2, lane);
            g_nbr[sidx * KNN + lane] = (int)(unsigned)(k2[0] & 0xffffffffull);
        } else if (C <= 128) {
            unsigned long long k4[4];
#pragma unroll
            for (int r = 0; r < 4; ++r) {
                const int v = r * 32 + lane;
                k4[r] = (v < C) ? lst[v] : 0xffffffffffffffffull;
            }
            bitonic_sort<4>(k4, lane);
            g_nbr[sidx * KNN + lane] = (int)(unsigned)(k4[0] & 0xffffffffull);
        } else {
            unsigned long long k8[8];
#pragma unroll
            for (int r = 0; r < 8; ++r) {
                const int v = r * 32 + lane;
                k8[r] = (v < C) ? lst[v] : 0xffffffffffffffffull;
            }
            bitonic_sort<8>(k8, lane);
            g_nbr[sidx * KNN + lane] = (int)(unsigned)(k8[0] & 0xffffffffull);
        }
    }
}

__device__ void xw1_body(const float* __restrict__ x,
                         const float* __restrict__ W1, char* smraw, int blk) {
    float* xs = (float*)smraw;            // 16 * 64 floats
    const int p0 = blk * 16;
    const int tid = threadIdx.x;
    for (int i = tid; i < 16 * DIN; i += 256) xs[i] = x[p0 * DIN + i];
    __syncthreads();

    const int j = tid & 127;
    const int h = tid >> 7;               // points 8h..8h+7
    float acc[8];
#pragma unroll
    for (int p = 0; p < 8; ++p) acc[p] = 0.f;
#pragma unroll
    for (int f = 0; f < DIN; ++f) {
        float w = W1[f * H1DIM + j];
#pragma unroll
        for (int p = 0; p < 8; ++p)
            acc[p] = fmaf(xs[(h * 8 + p) * DIN + f], w, acc[p]);
    }
#pragma unroll
    for (int p = 0; p < 8; ++p)
        g_xw1[(p0 + h * 8 + p) * H1DIM + j] = acc[p];
}

__device__ void w2frag_body(const float* __restrict__ W2, int blk) {
    const int idx  = blk * 256 + threadIdx.x;   // 0..16383
    const int lane = idx & 31;
    const int h    = (idx >> 5) & 1;
    const int t    = (idx >> 6) & 3;
    const int kt   = (idx >> 8) & 7;
    const int w    = (idx >> 11) & 7;

    const int k = kt * 16 + (lane & 3) * 2 + 8 * h;
    const int n = w * 32 + t * 8 + (lane >> 2);

    const __half p0 = __float2half_rn(W2[k * H2DIM + n]);
    const __half p1 = __float2half_rn(W2[(k + 1) * H2DIM + n]);
    unsigned short u0, u1;
    memcpy(&u0, &p0, 2);
    memcpy(&u1, &p1, 2);
    g_w2frag[idx] = (uint32_t)u0 | ((uint32_t)u1 << 16);
}

__global__ void __launch_bounds__(256) k_pre(const float* __restrict__ x,
                                             const float* __restrict__ pos,
                                             const float* __restrict__ W1,
                                             const float* __restrict__ W2) {
    extern __shared__ char smraw[];
    const int bid = blockIdx.x;
    if (bid < KNN_BLOCKS) {
        knn_body(pos, smraw, bid);
    } else if (bid < KNN_BLOCKS + XW1_BLOCKS) {
        xw1_body(x, W1, smraw, bid - KNN_BLOCKS);
    } else {
        w2frag_body(W2, bid - KNN_BLOCKS - XW1_BLOCKS);
    }
}

// ---------------------------------------------------------------------------
// Kernel 3: MLP + max-pool, persistent CTAs (R13 version, proven 160.7us).
// grid = 296 (2/SM); each block loops over sample-groups of 4.
// B-fragments loaded ONCE per block; metadata (npx/gix/psmp) in smem,
// ping-ponged so group g+1's LDGs overlap the tail of group g's GEMM.
// h1 single-buffered (the metadata->produce barrier orders reuse).
// ---------------------------------------------------------------------------
#define SPB3 4
#define NGRP (NSAMP / SPB3)                 // 2048
#define ROWSTRIDE 136                       // fp16 elements per h1 row
#define H1_BYTES  (SPB3 * 32 * ROWSTRIDE * 2)  // 34816
#define SM_DYN    H1_BYTES
#define MLP_GRID  296

__global__ void __launch_bounds__(256, 2) k_mlp(const float* __restrict__ pos,
                                                const float* __restrict__ W1,
                                                const float* __restrict__ b1,
                                                const float* __restrict__ b2,
                                                float* __restrict__ out,
                                                int write_extras) {
    extern __shared__ __align__(16) char dyn[];
    __half* h1s = (__half*)dyn;

    __shared__ float w1r[3][H1DIM];
    __shared__ float b1s[H1DIM];
    __shared__ float b2s[H2DIM];
    __shared__ float npx[2][128], npy[2][128], npz[2][128];
    __shared__ int   gix[2][128];
    __shared__ float psmp[2][4][3];

    const int tid  = threadIdx.x;
    const int lane = tid & 31;
    const int wid  = tid >> 5;

    // ---- B-fragments: 64 u32 per thread, loaded once per block ----
    uint32_t bfr[8][4][2];
    {
        const uint32_t* fb = g_w2frag + wid * 2048 + lane;
#pragma unroll
        for (int u = 0; u < 64; ++u) {
            const int kt = u >> 3, t = (u >> 1) & 3, h = u & 1;
            bfr[kt][t][h] = fb[u * 32];
        }
    }

    if (tid < H1DIM) {
        w1r[0][tid] = W1[64 * H1DIM + tid];
        w1r[1][tid] = W1[65 * H1DIM + tid];
        w1r[2][tid] = W1[66 * H1DIM + tid];
        b1s[tid]    = b1[tid];
    }
    b2s[tid] = b2[tid];

    const uint32_t h1_u = smem_u32(h1s);
    const int j    = tid & 127;           // hidden channel
    const int half = tid >> 7;            // neighbor parity
    const int lrow = lane & 15;
    const int lcol = (lane >> 4) & 1;

    for (int g = blockIdx.x; g < NGRP; g += gridDim.x) {
        const int buf = (g / gridDim.x) & 1;

        // ---- metadata for this group (overlaps prior group's GEMM) ----
        if (tid < 128) {
            const int si = tid >> 5;
            const int s  = g * 4 + si;
            const int b  = s >> 10;
            const int nl = g_nbr[s * KNN + (tid & 31)];
            const int gg = b * NP + nl;
            gix[buf][tid] = gg;
            npx[buf][tid] = pos[3 * gg];
            npy[buf][tid] = pos[3 * gg + 1];
            npz[buf][tid] = pos[3 * gg + 2];
        }
        if (tid < 16) {                    // covers psmp[buf][0..3]
            const int si = tid >> 2, c = tid & 3;
            if (c < 3) {
                const int s = g * 4 + si;
                const int b = s >> 10;
                const int p = b * NP + (s & (NS - 1)) * STRIDE;
                psmp[buf][si][c] = pos[3 * p + c];
            }
        }
        __syncthreads();   // S1: meta visible; also GEMM(g-1) done -> h1 free

        // ---- h1 production: fp32 -> fp16 into padded smem rows ----
#pragma unroll
        for (int si = 0; si < 4; ++si) {
            const float psx = psmp[buf][si][0];
            const float psy = psmp[buf][si][1];
            const float psz = psmp[buf][si][2];
#pragma unroll
            for (int kk = 0; kk < 16; ++kk) {
                const int k = kk * 2 + half;
                const int gg = gix[buf][si * 32 + k];
                float rx = npx[buf][si * 32 + k] - psx;
                float ry = npy[buf][si * 32 + k] - psy;
                float rz = npz[buf][si * 32 + k] - psz;
                float v = g_xw1[gg * H1DIM + j];
                v = fmaf(rx, w1r[0][j], v);
                v = fmaf(ry, w1r[1][j], v);
                v = fmaf(rz, w1r[2][j], v);
                v += b1s[j];
                v = fmaxf(v, 0.f);
                h1s[(si * 32 + k) * ROWSTRIDE + j] = __float2half_rn(v);
            }
        }
        __syncthreads();   // S2: h1 ready

        // ---- per-sample GEMM + max-pool ----
        for (int s4 = 0; s4 < 4; ++s4) {
            float acc[2][4][4];
#pragma unroll
            for (int mt = 0; mt < 2; ++mt)
#pragma unroll
                for (int nt = 0; nt < 4; ++nt)
#pragma unroll
                    for (int e = 0; e < 4; ++e) acc[mt][nt][e] = 0.f;

#pragma unroll
            for (int kt = 0; kt < 8; ++kt) {
                uint32_t afr[2][4];
#pragma unroll
                for (int mt = 0; mt < 2; ++mt) {
                    const uint32_t byteoff =
                        (uint32_t)(((s4 * 32 + mt * 16 + lrow) * ROWSTRIDE +
                                    kt * 16 + lcol * 8) * 2);
                    ldm_x4(afr[mt], h1_u + byteoff);
                }
#pragma unroll
                for (int mt = 0; mt < 2; ++mt)
#pragma unroll
                    for (int nt = 0; nt < 4; ++nt)
                        mma_f16(acc[mt][nt], afr[mt], bfr[kt][nt]);
            }

            const int s = g * 4 + s4;
#pragma unroll
            for (int nt = 0; nt < 4; ++nt)
#pragma unroll
                for (int par = 0; par < 2; ++par) {
                    float m = fmaxf(fmaxf(acc[0][nt][par], acc[0][nt][par + 2]),
                                    fmaxf(acc[1][nt][par], acc[1][nt][par + 2]));
                    m = fmaxf(m, __shfl_xor_sync(0xffffffffu, m, 4));
                    m = fmaxf(m, __shfl_xor_sync(0xffffffffu, m, 8));
                    m = fmaxf(m, __shfl_xor_sync(0xffffffffu, m, 16));
                    if (lane < 4) {
                        const int c = wid * 32 + nt * 8 + (lane & 3) * 2 + par;
                        out[XOUT_OFF + s * H2DIM + c] = fmaxf(m + b2s[c], 0.f);
                    }
                }
        }

        if (write_extras) {
#pragma unroll
            for (int si = 0; si < 4; ++si) {
                const int s = g * 4 + si;
                const int b = s >> 10;
                const int p = b * NP + (s & (NS - 1)) * STRIDE;
                if (tid < 3)  out[POS_OFF + s * 3 + tid] = psmp[buf][si][tid];
                if (tid == 3) out[BATCH_OFF + s] = (float)b;
                if (tid == 4) out[IDX_OFF + s]   = (float)p;
            }
        }
        // no trailing sync: next iteration writes the OTHER metadata buffer,
        // and S1 there orders h1 reuse.
    }
}

// ---------------------------------------------------------------------------
extern "C" void kernel_launch(void* const* d_in, const int* in_sizes, int n_in,
                              void* d_out, int out_size) {
    const float* x   = (const float*)d_in[0];
    const float* pos = (const float*)d_in[1];
    const float* W1  = (const float*)d_in[3];
    const float* b1  = (const float*)d_in[4];
    const float* W2  = (const float*)d_in[5];
    const float* b2  = (const float*)d_in[6];
    float* out = (float*)d_out;

    const int write_extras = (out_size >= TOTAL_OUT) ? 1 : 0;

    cudaFuncSetAttribute(k_pre, cudaFuncAttributeMaxDynamicSharedMemorySize,
                         PRE_SMEM);
    k_pre<<<PRE_GRID, 256, PRE_SMEM>>>(x, pos, W1, W2);

    cudaFuncSetAttribute(k_mlp, cudaFuncAttributeMaxDynamicSharedMemorySize,
                         SM_DYN);
    k_mlp<<<MLP_GRID, 256, SM_DYN>>>(pos, W1, b1, b2, out, write_extras);
}